// round 11
// baseline (speedup 1.0000x reference)
#include <cuda_runtime.h>
#include <cuda_bf16.h>
#include <cstdint>
#include <cstddef>

// ---------------------------------------------------------------------------
// TaggingFNNDecoder: 2-layer LSTM tag decoder. B=32, T=256, D=1024, H=512, K=128
// Round 10: 2 CTAs/SM (G=256, 256 thr, 2 units/CTA, 73KB smem,
// __launch_bounds__(256,2)) to double warps/SMSP; direct gate reduction
// (no rowsum stage); dot64 hybrid lanes (4 rows x 2 batches).
// ---------------------------------------------------------------------------

#define B_  32
#define T_  256
#define D_  1024
#define H_  512
#define K_  128
#define R_  2048    // 4*H gate rows
#define KC0 640     // cell0 reduced k-dim: h1(512) + e(128)
#define KC1 1024    // cell1 k-dim: h1(512) + h2(512)
#define G_  256     // persistent grid size (2 CTAs/SM on 148 SMs)
#define PS  34      // padded row stride for partial arrays (8B-aligned pairs)
#define LROW 128    // interleaved logits row stride (floats per tag)

// ------------------------- device scratch ----------------------------------
__device__ float d_pre0[(size_t)T_ * R_ * B_];   // 64 MB [t][row][b]
__device__ float d_W0[(size_t)R_ * KC0];         // [row][ W_hh0 | W_ih0[:,1024:] ]
__device__ float d_W1[(size_t)R_ * KC1];         // [row][ W_ih1 | W_hh1 ]
__device__ float d_bias1[R_];
__device__ float d_h1[2 * H_ * B_];              // double buffered [j][b]
__device__ float d_h2[2 * H_ * B_];
__device__ float d_c1[H_ * B_];
__device__ float d_c2[H_ * B_];
__device__ float d_logit0[K_ * LROW];            // interleaved initial logits
__device__ float d_logits[(size_t)T_ * K_ * LROW]; // interleaved raw logits

// central barrier counter (monotonic within one launch; reset by k_zero)
__device__ unsigned g_count;

// fast NaN-free activations (errors ~1e-7, well under 1e-3 tolerance)
__device__ __forceinline__ float sigf(float x) {
    return __fdividef(1.0f, 1.0f + __expf(-x));
}
__device__ __forceinline__ float tanhfast(float x) {
    return 1.0f - __fdividef(2.0f, 1.0f + __expf(2.0f * x));
}

// packed fp32x2 helpers
__device__ __forceinline__ unsigned long long pk2(float x) {
    unsigned long long r; unsigned u = __float_as_uint(x);
    asm("mov.b64 %0, {%1, %1};" : "=l"(r) : "r"(u));
    return r;
}
__device__ __forceinline__ void fma2(unsigned long long& a,
                                     unsigned long long x, unsigned long long w) {
    asm("fma.rn.f32x2 %0, %1, %2, %0;" : "+l"(a) : "l"(x), "l"(w));
}
__device__ __forceinline__ void unpk2(float& lo, float& hi, unsigned long long v) {
    unsigned l, h;
    asm("mov.b64 {%0, %1}, %2;" : "=r"(l), "=r"(h) : "l"(v));
    lo = __uint_as_float(l); hi = __uint_as_float(h);
}

// split grid barrier: arrive = syncthreads + red.release.gpu; wait = acquire-spin
__device__ __forceinline__ void gbar_arrive() {
    __syncthreads();
    if (threadIdx.x == 0) {
        asm volatile("red.release.gpu.add.u32 [%0], %1;"
                     :: "l"(&g_count), "r"(1u) : "memory");
    }
}
__device__ __forceinline__ void gbar_wait(unsigned target) {
    if (threadIdx.x == 0) {
        unsigned v;
        do {
            asm volatile("ld.acquire.gpu.u32 %0, [%1];"
                         : "=r"(v) : "l"(&g_count) : "memory");
        } while ((int)(v - target) < 0);
    }
    __syncthreads();
}

// hybrid dot body: warp covers 64-k slice; lane = (r4 in {0,4}, b2 = 2*(lane&15))
// computes rows r4..r4+3 x batches b2,b2+1 (one packed pair per row).
__device__ __forceinline__ void dot64(unsigned long long acc[4],
                                      const float* __restrict__ wbase,
                                      const float* __restrict__ xsrc,
                                      int r4, int b2) {
#pragma unroll 8
    for (int kk = 0; kk < 64; kk++) {
        float4 wv = *(const float4*)(wbase + kk * 8 + r4);
        unsigned long long x01;
        asm("ld.global.cg.b64 %0, [%1];"
            : "=l"(x01) : "l"(xsrc + kk * 32 + b2));
        fma2(acc[0], x01, pk2(wv.x));
        fma2(acc[1], x01, pk2(wv.y));
        fma2(acc[2], x01, pk2(wv.z));
        fma2(acc[3], x01, pk2(wv.w));
    }
}

// store packed pairs: 4 STS.64 (PS=34 keeps 8B alignment for even b2)
__device__ __forceinline__ void store_acc(float* part, int wbase_row,
                                          unsigned long long acc[4],
                                          int r4, int b2) {
#pragma unroll
    for (int rr = 0; rr < 4; rr++) {
        *(unsigned long long*)(part + (wbase_row + r4 + rr) * PS + b2) = acc[rr];
    }
}

// -------------------- setup: pack weights + init states ---------------------
__global__ void k_setup(const float* __restrict__ Wih0, const float* __restrict__ Whh0,
                        const float* __restrict__ Wih1, const float* __restrict__ Whh1,
                        const float* __restrict__ bih1, const float* __restrict__ bhh1,
                        const float* __restrict__ h_t,  const float* __restrict__ c_t,
                        const float* __restrict__ hid,  const float* __restrict__ W_out,
                        const float* __restrict__ b_out) {
    int row = blockIdx.x;          // 0..2047
    int tid = threadIdx.x;         // 256 threads
    // ---- weight pack ----
    const float4* s1 = (const float4*)(Whh0 + (size_t)row * H_);
    float4* dW0 = (float4*)(d_W0 + (size_t)row * KC0);
    for (int i = tid; i < H_ / 4; i += 256) dW0[i] = s1[i];
    const float4* s2 = (const float4*)(Wih0 + (size_t)row * (D_ + K_) + D_);
    for (int i = tid; i < K_ / 4; i += 256) dW0[H_ / 4 + i] = s2[i];
    float4* dW1 = (float4*)(d_W1 + (size_t)row * KC1);
    const float4* s3 = (const float4*)(Wih1 + (size_t)row * H_);
    const float4* s4 = (const float4*)(Whh1 + (size_t)row * H_);
    for (int i = tid; i < H_ / 4; i += 256) { dW1[i] = s3[i]; dW1[H_ / 4 + i] = s4[i]; }
    if (tid == 0) d_bias1[row] = bih1[row] + bhh1[row];

    // ---- logits prefill with output bias (blocks 0..255 <-> t) ----
    if (row < 256) {
        float* dst = d_logits + (size_t)row * K_ * LROW;
        for (int i = tid; i < K_ * LROW; i += 256) dst[i] = b_out[i >> 7];
    }
    // ---- state transpose (blocks 0..63) ----
    if (row < 64) {
        int idx = row * 256 + tid;                 // 0..16383 = j*32+b
        int j = idx >> 5, b = idx & 31;
        d_h1[idx] = h_t[b * H_ + j];
        d_h2[idx] = h_t[B_ * H_ + b * H_ + j];
        d_c1[idx] = c_t[b * H_ + j];
        d_c2[idx] = c_t[B_ * H_ + b * H_ + j];
    }
    // ---- initial tag logits (blocks 64..95, threads 0..127) ----
    if (row >= 64 && row < 96 && tid < 128) {
        int b = row - 64;                          // batch
        int k = tid;                               // tag
        const float* x  = hid + (size_t)b * T_ * D_;
        const float* wr = W_out + (size_t)k * H_;
        float a0 = 0.f, a1 = 0.f, a2 = 0.f, a3 = 0.f;
        for (int j = 0; j < H_; j += 4) {
            float4 w4 = *(const float4*)(wr + j);
            a0 += w4.x * x[j + 0];
            a1 += w4.y * x[j + 1];
            a2 += w4.z * x[j + 2];
            a3 += w4.w * x[j + 3];
        }
        d_logit0[k * LROW + ((b & 3) << 5) + (b >> 2)] =
            (a0 + a1) + (a2 + a3) + b_out[k];
    }
}

// reset barrier counter
__global__ void k_zero() {
    if (threadIdx.x == 0) g_count = 0;
}

// -------------- pre-projection SGEMM (FFMA2, K-tile 16; R7 version) ----------
__global__ void __launch_bounds__(256) k_pre(const float* __restrict__ A,
                                             const float* __restrict__ W,
                                             const float* __restrict__ bih,
                                             const float* __restrict__ bhh) {
    __shared__ float As[16][132];
    __shared__ float Bs[16][132];
    int tid = threadIdx.x;
    int m0 = blockIdx.y * 128;
    int n0 = blockIdx.x * 128;
    int lr = tid >> 1;
    int lc = (tid & 1) * 4;
    int ty = tid >> 4;
    int tx = tid & 15;

    unsigned long long acc2[8][4];
#pragma unroll
    for (int i = 0; i < 8; i++)
#pragma unroll
        for (int j = 0; j < 4; j++) acc2[i][j] = 0ull;

    for (int kt = 0; kt < D_; kt += 16) {
        float4 a0 = *(const float4*)&A[(size_t)(m0 + lr) * D_ + kt + lc];
        float4 a1 = *(const float4*)&A[(size_t)(m0 + lr) * D_ + kt + 8 + lc];
        float4 b0 = *(const float4*)&W[(size_t)(n0 + lr) * (D_ + K_) + kt + lc];
        float4 b1 = *(const float4*)&W[(size_t)(n0 + lr) * (D_ + K_) + kt + 8 + lc];
        As[lc + 0][lr] = a0.x; As[lc + 1][lr] = a0.y;
        As[lc + 2][lr] = a0.z; As[lc + 3][lr] = a0.w;
        As[8 + lc + 0][lr] = a1.x; As[8 + lc + 1][lr] = a1.y;
        As[8 + lc + 2][lr] = a1.z; As[8 + lc + 3][lr] = a1.w;
        Bs[lc + 0][lr] = b0.x; Bs[lc + 1][lr] = b0.y;
        Bs[lc + 2][lr] = b0.z; Bs[lc + 3][lr] = b0.w;
        Bs[8 + lc + 0][lr] = b1.x; Bs[8 + lc + 1][lr] = b1.y;
        Bs[8 + lc + 2][lr] = b1.z; Bs[8 + lc + 3][lr] = b1.w;
        __syncthreads();
#pragma unroll 16
        for (int k = 0; k < 16; k++) {
            float4 raA = *(const float4*)&As[k][ty * 4];
            float4 raB = *(const float4*)&As[k][64 + ty * 4];
            ulonglong2 rbA = *(const ulonglong2*)&Bs[k][tx * 4];
            ulonglong2 rbB = *(const ulonglong2*)&Bs[k][64 + tx * 4];
            float ra[8] = {raA.x, raA.y, raA.z, raA.w, raB.x, raB.y, raB.z, raB.w};
#pragma unroll
            for (int i = 0; i < 8; i++) {
                unsigned long long ax = pk2(ra[i]);
                fma2(acc2[i][0], ax, rbA.x);
                fma2(acc2[i][1], ax, rbA.y);
                fma2(acc2[i][2], ax, rbB.x);
                fma2(acc2[i][3], ax, rbB.y);
            }
        }
        __syncthreads();
    }

#pragma unroll
    for (int i = 0; i < 8; i++) {
        int m = m0 + ((i < 4) ? (ty * 4 + i) : (64 + ty * 4 + i - 4));
        int tt = m & 255;
        int bb = m >> 8;
#pragma unroll
        for (int j2 = 0; j2 < 4; j2++) {
            float lo, hi;
            unpk2(lo, hi, acc2[i][j2]);
            int nb = (j2 < 2) ? (n0 + tx * 4 + j2 * 2)
                              : (n0 + 64 + tx * 4 + (j2 - 2) * 2);
            d_pre0[((size_t)tt * R_ + nb + 0) * B_ + bb] = lo + bih[nb] + bhh[nb];
            d_pre0[((size_t)tt * R_ + nb + 1) * B_ + bb] = hi + bih[nb + 1] + bhh[nb + 1];
        }
    }
}

// ------------------------- persistent recurrence -----------------------------
// 256 CTAs x 256 threads (8 warps), 2 CTAs/SM. CTA c owns units u = c*2, c*2+1
// (8 gate rows per layer: row r = g*2+ul, global grow = g*512 + c*2 + ul).
__global__ void __launch_bounds__(256, 2) k_loop(const float* __restrict__ W_out,
                                                 const float* __restrict__ b_out) {
    extern __shared__ float smem[];
    float* w0s     = smem;                    // 640*8  = 5120
    float* w1s     = w0s + KC0 * 8;           // 1024*8 = 8192
    float* woutT   = w1s + KC1 * 8;           // [ul][k] 2*128 = 256
    float* bias1s  = woutT + 256;             // 8 (padded to 32)
    float* parthA  = bias1s + 32;             // 64*PS = 2176 (cell0 h partials)
    float* partB   = parthA + 64 * PS;        // 2176 (e / cell1 partials)
    float* zps     = partB + 64 * PS;         // 8*32 = 256
    float* h2s     = zps + 256;               // 2*32 = 64

    const int c    = blockIdx.x;
    const int tid  = threadIdx.x;
    const int lane = tid & 31;
    const int w    = tid >> 5;                // 8 warps
    const int r4   = (lane >> 4) << 2;        // row-group base: 0 or 4
    const int b2   = (lane & 15) << 1;        // batch-pair base
    const int bo   = ((lane & 3) << 5) + (lane >> 2);  // interleaved logit offset

    // ---- stage weights into SMEM (once) ----
#pragma unroll
    for (int r = 0; r < 8; r++) {
        int grow = (r >> 1) * H_ + c * 2 + (r & 1);
        const float* src0 = d_W0 + (size_t)grow * KC0;
        for (int k = tid; k < KC0; k += 256) w0s[k * 8 + r] = src0[k];
        const float* src1 = d_W1 + (size_t)grow * KC1;
        for (int k = tid; k < KC1; k += 256) w1s[k * 8 + r] = src1[k];
        if (tid == 0) bias1s[r] = d_bias1[grow];
    }
    {   // W_out columns for this CTA's 2 units: woutT[ul*128 + k]
        int ul2 = tid >> 7, k2 = tid & 127;
        woutT[tid] = W_out[(size_t)k2 * H_ + c * 2 + ul2];
    }
    __syncthreads();

    // ---- per-thread cell state (tid<64): b = tid&31, ul = tid>>5 ----
    float c1_reg = 0.f, c2_reg = 0.f;
    int b = tid & 31, ul = tid >> 5;          // ul 0..7; only ul<2 used
    int u = c * 2 + (ul & 1);
    float pre[4];
    if (tid < 64) {
        c1_reg = d_c1[u * 32 + b];
        c2_reg = d_c2[u * 32 + b];
#pragma unroll
        for (int g = 0; g < 4; g++)
            pre[g] = __ldcg(&d_pre0[((size_t)0 * R_ + g * H_ + u) * B_ + b]);
    }

    // ---- prologue: cell0 h-part partials for t=0 (h1 buffer 0) ----
    {
        unsigned long long acc[4] = {0ull, 0ull, 0ull, 0ull};
        dot64(acc, w0s + (w * 64) * 8, d_h1 + (w * 64) * 32, r4, b2);
        store_acc(parthA, w * 8, acc, r4, b2);
    }
    __syncthreads();

    unsigned tgt = G_;

    for (int t = 0; t < T_; t++) {
        const int old = t & 1, nw = old ^ 1;
        float*       __restrict__ h1new = d_h1 + nw  * (H_ * B_);
        const float* __restrict__ h2old = d_h2 + old * (H_ * B_);
        float*       __restrict__ h2new = d_h2 + nw  * (H_ * B_);

        // ======================= phase A: e-dot ==============================
        {
            unsigned long long acce[4] = {0ull, 0ull, 0ull, 0ull};
            const float* lg = (t == 0) ? d_logit0
                                       : d_logits + (size_t)(t - 1) * (K_ * LROW);
            float zp = 0.f;
            int ke0 = w * 16;
#pragma unroll
            for (int kk = 0; kk < 16; kk++) {
                float ev = __expf(__ldcg(lg + (ke0 + kk) * LROW + bo));
                zp += ev;
                unsigned long long xx = pk2(ev);
                const ulonglong2* q = (const ulonglong2*)(w0s + (H_ + ke0 + kk) * 8);
                ulonglong2 q0 = q[0], q1 = q[1];
                fma2(acce[0], xx, q0.x); fma2(acce[1], xx, q0.y);
                fma2(acce[2], xx, q1.x); fma2(acce[3], xx, q1.y);
            }
            zps[w * 32 + lane] = zp;
#pragma unroll
            for (int p = 0; p < 4; p++) {
                float lo, hi; unpk2(lo, hi, acce[p]);
                partB[(w * 8 + 2 * p + 0) * PS + lane] = lo;
                partB[(w * 8 + 2 * p + 1) * PS + lane] = hi;
            }
        }
        __syncthreads();

        // gate0: 64 threads, direct reduction over 8 warps' partials
        if (tid < 64) {
            float Z = 0.f;
#pragma unroll
            for (int w2 = 0; w2 < 8; w2++) Z += zps[w2 * 32 + b];
            float invZ = __fdividef(1.0f, Z);
            float gate[4];
#pragma unroll
            for (int g = 0; g < 4; g++) {
                int r = g * 2 + (ul & 1);
                float sh = pre[g], se = 0.f;
#pragma unroll
                for (int w2 = 0; w2 < 8; w2++) {
                    sh += parthA[(w2 * 8 + r) * PS + b];
                    se += partB[(w2 * 8 + r) * PS + b];
                }
                gate[g] = sh + se * invZ;
            }
            float iv = sigf(gate[0]);
            float fv = sigf(gate[1]);
            float gv = tanhfast(gate[2]);
            float ov = sigf(gate[3]);
            c1_reg = fv * c1_reg + iv * gv;
            h1new[u * 32 + b] = ov * tanhfast(c1_reg);
        }
        gbar_arrive();                          // bar1 arrive

        // ===== cell1 dot: h2-half (no h1 dependency) overlaps bar1 wait ======
        unsigned long long acc1[4] = {0ull, 0ull, 0ull, 0ull};
        dot64(acc1, w1s + (H_ + w * 64) * 8, h2old + (w * 64) * 32, r4, b2);
        gbar_wait(tgt); tgt += G_;              // bar1 wait (h1[t] now global)

        // ======================= phase B: cell1 h1-half ======================
        dot64(acc1, w1s + (w * 64) * 8, h1new + (w * 64) * 32, r4, b2);
        store_acc(partB, w * 8, acc1, r4, b2);
        __syncthreads();

        if (tid < 64) {
            float gate[4];
#pragma unroll
            for (int g = 0; g < 4; g++) {
                int r = g * 2 + (ul & 1);
                float s = bias1s[r];
#pragma unroll
                for (int w2 = 0; w2 < 8; w2++) s += partB[(w2 * 8 + r) * PS + b];
                gate[g] = s;
            }
            float iv = sigf(gate[0]);
            float fv = sigf(gate[1]);
            float gv = tanhfast(gate[2]);
            float ov = sigf(gate[3]);
            c2_reg = fv * c2_reg + iv * gv;
            float h2v = ov * tanhfast(c2_reg);
            h2new[u * 32 + b] = h2v;
            h2s[(ul & 1) * 32 + b] = h2v;
        }
        __syncthreads();

        // scatter: warp w owns tags k = w*16..w*16+15; lane = batch (interleaved)
        {
            float h0 = h2s[lane];
            float h1v = h2s[32 + lane];
            float* dstl = d_logits + (size_t)t * (K_ * LROW);
            int k0 = w * 16;
#pragma unroll
            for (int kk = 0; kk < 16; kk++) {
                int kq = k0 + kk;
                float v = woutT[kq] * h0 + woutT[128 + kq] * h1v;
                atomicAdd(dstl + kq * LROW + bo, v);
            }
        }
        // prefetch pre0 for next step
        if (tid < 64) {
            int tn = (t + 1 < T_) ? (t + 1) : t;
#pragma unroll
            for (int g = 0; g < 4; g++)
                pre[g] = __ldcg(&d_pre0[((size_t)tn * R_ + g * H_ + u) * B_ + b]);
        }
        gbar_arrive();                          // bar2 arrive

        // ==== cell0 h-part dot for step t+1 (uses h1[t]) overlaps bar2 =======
        {
            unsigned long long acc[4] = {0ull, 0ull, 0ull, 0ull};
            dot64(acc, w0s + (w * 64) * 8, h1new + (w * 64) * 32, r4, b2);
            store_acc(parthA, w * 8, acc, r4, b2);
        }
        gbar_wait(tgt); tgt += G_;              // bar2 wait (logits[t] global)
    }
}

// --------------------------- final masked softmax ----------------------------
__global__ void __launch_bounds__(256) k_final(const float* __restrict__ mask,
                                               float* __restrict__ out) {
    int tid = threadIdx.x, lane = tid & 31, w = tid >> 5;
    int gidx = blockIdx.x * 8 + w;             // 0..8191
    int b = gidx >> 8, t = gidx & 255;
    float pen = (1.0f - mask[b * T_ + t]) * -1e32f;
    int bo = ((b & 3) << 5) + (b >> 2);
    float v[4];
#pragma unroll
    for (int i = 0; i < 4; i++)
        v[i] = d_logits[(size_t)t * (K_ * LROW) + (lane + 32 * i) * LROW + bo] + pen;
    float mx = fmaxf(fmaxf(v[0], v[1]), fmaxf(v[2], v[3]));
#pragma unroll
    for (int o = 16; o > 0; o >>= 1) mx = fmaxf(mx, __shfl_xor_sync(~0u, mx, o));
    float s = 0.f;
#pragma unroll
    for (int i = 0; i < 4; i++) { v[i] = __expf(v[i] - mx); s += v[i]; }
#pragma unroll
    for (int o = 16; o > 0; o >>= 1) s += __shfl_xor_sync(~0u, s, o);
    float inv = 1.0f / s;
#pragma unroll
    for (int i = 0; i < 4; i++)
        out[((size_t)b * T_ + t) * K_ + lane + 32 * i] = v[i] * inv;
}

// ----------------------------------------------------------------------------
extern "C" void kernel_launch(void* const* d_in, const int* in_sizes, int n_in,
                              void* d_out, int out_size) {
    const float* hiddens = (const float*)d_in[0];
    const float* h_t     = (const float*)d_in[1];
    const float* c_t     = (const float*)d_in[2];
    const float* mask    = (const float*)d_in[3];
    const float* W_out   = (const float*)d_in[4];
    const float* b_out   = (const float*)d_in[5];
    const float* W_ih0   = (const float*)d_in[6];
    const float* W_hh0   = (const float*)d_in[7];
    const float* b_ih0   = (const float*)d_in[8];
    const float* b_hh0   = (const float*)d_in[9];
    const float* W_ih1   = (const float*)d_in[10];
    const float* W_hh1   = (const float*)d_in[11];
    const float* b_ih1   = (const float*)d_in[12];
    const float* b_hh1   = (const float*)d_in[13];
    float* out = (float*)d_out;

    // SMEM floats: 5120+8192+256+32 + 2176 + 2176 + 256 + 64 = 18272
    // = 73088 bytes -> two CTAs per SM (146176 <= 228KB)
    const int SMEM_LOOP = 18272 * 4;
    cudaFuncSetAttribute(k_loop, cudaFuncAttributeMaxDynamicSharedMemorySize, SMEM_LOOP);

    // launch order: slot 3 (the one ncu captures) = k_loop
    k_setup<<<R_, 256>>>(W_ih0, W_hh0, W_ih1, W_hh1, b_ih1, b_hh1,
                         h_t, c_t, hiddens, W_out, b_out);
    k_pre<<<dim3(16, 64), 256>>>(hiddens, W_ih0, b_ih0, b_hh0);
    k_zero<<<1, 32>>>();
    k_loop<<<G_, 256, SMEM_LOOP>>>(W_out, b_out);
    k_final<<<1024, 256>>>(mask, out);
}

// round 12
// speedup vs baseline: 1.1234x; 1.1234x over previous
#include <cuda_runtime.h>
#include <cuda_bf16.h>
#include <cstdint>
#include <cstddef>

// ---------------------------------------------------------------------------
// TaggingFNNDecoder: 2-layer LSTM tag decoder. B=32, T=256, D=1024, H=512, K=128
// Round 11: loop reverted to R9 (best). k_pre rebuilt for occupancy:
// 128x64 tile, 256 thr, 4x8/thread, __launch_bounds__(256,4) -> 4 CTAs/SM.
// ---------------------------------------------------------------------------

#define B_  32
#define T_  256
#define D_  1024
#define H_  512
#define K_  128
#define R_  2048    // 4*H gate rows
#define KC0 640     // cell0 reduced k-dim: h1(512) + e(128)
#define KC1 1024    // cell1 k-dim: h1(512) + h2(512)
#define G_  128     // persistent grid size (1 CTA/SM)
#define PS  34      // padded row stride for partial arrays (8B-aligned pairs)
#define LROW 128    // interleaved logits row stride (floats per tag)

// ------------------------- device scratch ----------------------------------
__device__ float d_pre0[(size_t)T_ * R_ * B_];   // 64 MB [t][row][b]
__device__ float d_W0[(size_t)R_ * KC0];         // [row][ W_hh0 | W_ih0[:,1024:] ]
__device__ float d_W1[(size_t)R_ * KC1];         // [row][ W_ih1 | W_hh1 ]
__device__ float d_bias1[R_];
__device__ float d_h1[2 * H_ * B_];              // double buffered [j][b]
__device__ float d_h2[2 * H_ * B_];
__device__ float d_c1[H_ * B_];
__device__ float d_c2[H_ * B_];
__device__ float d_logit0[K_ * LROW];            // interleaved initial logits
__device__ float d_logits[(size_t)T_ * K_ * LROW]; // interleaved raw logits

// central barrier counter (monotonic within one launch; reset by k_zero)
__device__ unsigned g_count;

// fast NaN-free activations (errors ~1e-7, well under 1e-3 tolerance)
__device__ __forceinline__ float sigf(float x) {
    return __fdividef(1.0f, 1.0f + __expf(-x));
}
__device__ __forceinline__ float tanhfast(float x) {
    return 1.0f - __fdividef(2.0f, 1.0f + __expf(2.0f * x));
}

// packed fp32x2 helpers
__device__ __forceinline__ unsigned long long pk2(float x) {
    unsigned long long r; unsigned u = __float_as_uint(x);
    asm("mov.b64 %0, {%1, %1};" : "=l"(r) : "r"(u));
    return r;
}
__device__ __forceinline__ void fma2(unsigned long long& a,
                                     unsigned long long x, unsigned long long w) {
    asm("fma.rn.f32x2 %0, %1, %2, %0;" : "+l"(a) : "l"(x), "l"(w));
}
__device__ __forceinline__ void unpk2(float& lo, float& hi, unsigned long long v) {
    unsigned l, h;
    asm("mov.b64 {%0, %1}, %2;" : "=r"(l), "=r"(h) : "l"(v));
    lo = __uint_as_float(l); hi = __uint_as_float(h);
}

// split grid barrier: arrive = syncthreads + red.release.gpu; wait = acquire-spin
__device__ __forceinline__ void gbar_arrive() {
    __syncthreads();
    if (threadIdx.x == 0) {
        asm volatile("red.release.gpu.add.u32 [%0], %1;"
                     :: "l"(&g_count), "r"(1u) : "memory");
    }
}
__device__ __forceinline__ void gbar_wait(unsigned target) {
    if (threadIdx.x == 0) {
        unsigned v;
        do {
            asm volatile("ld.acquire.gpu.u32 %0, [%1];"
                         : "=r"(v) : "l"(&g_count) : "memory");
        } while ((int)(v - target) < 0);
    }
    __syncthreads();
}

// hybrid dot body: warp covers 32-k slice; lane = (r4, b8) computes rows
// r4..r4+3 x batches b4..b4+3. x loaded as two packed 64-bit pairs directly.
__device__ __forceinline__ void dot32(unsigned long long acc[4][2],
                                      const float* __restrict__ wbase,
                                      const float* __restrict__ xsrc,
                                      int r4, int b4) {
#pragma unroll 8
    for (int kk = 0; kk < 32; kk++) {
        float4 wv = *(const float4*)(wbase + kk * 16 + r4);
        unsigned long long x01, x23;
        asm("ld.global.cg.v2.b64 {%0,%1}, [%2];"
            : "=l"(x01), "=l"(x23) : "l"(xsrc + kk * 32 + b4));
        unsigned long long w0p = pk2(wv.x), w1p = pk2(wv.y);
        unsigned long long w2p = pk2(wv.z), w3p = pk2(wv.w);
        fma2(acc[0][0], x01, w0p); fma2(acc[0][1], x23, w0p);
        fma2(acc[1][0], x01, w1p); fma2(acc[1][1], x23, w1p);
        fma2(acc[2][0], x01, w2p); fma2(acc[2][1], x23, w2p);
        fma2(acc[3][0], x01, w3p); fma2(acc[3][1], x23, w3p);
    }
}

// store packed pairs directly: 8 STS.64 (PS=34 keeps 8B alignment)
__device__ __forceinline__ void store_acc(float* part, int wbase_row,
                                          unsigned long long acc[4][2],
                                          int r4, int b4) {
#pragma unroll
    for (int rr = 0; rr < 4; rr++) {
        unsigned long long* p =
            (unsigned long long*)(part + (wbase_row + r4 + rr) * PS + b4);
        p[0] = acc[rr][0];
        p[1] = acc[rr][1];
    }
}

// -------------------- setup: pack weights + init states ---------------------
__global__ void k_setup(const float* __restrict__ Wih0, const float* __restrict__ Whh0,
                        const float* __restrict__ Wih1, const float* __restrict__ Whh1,
                        const float* __restrict__ bih1, const float* __restrict__ bhh1,
                        const float* __restrict__ h_t,  const float* __restrict__ c_t,
                        const float* __restrict__ hid,  const float* __restrict__ W_out,
                        const float* __restrict__ b_out) {
    int row = blockIdx.x;          // 0..2047
    int tid = threadIdx.x;         // 256 threads
    // ---- weight pack ----
    const float4* s1 = (const float4*)(Whh0 + (size_t)row * H_);
    float4* dW0 = (float4*)(d_W0 + (size_t)row * KC0);
    for (int i = tid; i < H_ / 4; i += 256) dW0[i] = s1[i];
    const float4* s2 = (const float4*)(Wih0 + (size_t)row * (D_ + K_) + D_);
    for (int i = tid; i < K_ / 4; i += 256) dW0[H_ / 4 + i] = s2[i];
    float4* dW1 = (float4*)(d_W1 + (size_t)row * KC1);
    const float4* s3 = (const float4*)(Wih1 + (size_t)row * H_);
    const float4* s4 = (const float4*)(Whh1 + (size_t)row * H_);
    for (int i = tid; i < H_ / 4; i += 256) { dW1[i] = s3[i]; dW1[H_ / 4 + i] = s4[i]; }
    if (tid == 0) d_bias1[row] = bih1[row] + bhh1[row];

    // ---- logits prefill with output bias (blocks 0..255 <-> t) ----
    if (row < 256) {
        float* dst = d_logits + (size_t)row * K_ * LROW;
        for (int i = tid; i < K_ * LROW; i += 256) dst[i] = b_out[i >> 7];
    }
    // ---- state transpose (blocks 0..63) ----
    if (row < 64) {
        int idx = row * 256 + tid;                 // 0..16383 = j*32+b
        int j = idx >> 5, b = idx & 31;
        d_h1[idx] = h_t[b * H_ + j];
        d_h2[idx] = h_t[B_ * H_ + b * H_ + j];
        d_c1[idx] = c_t[b * H_ + j];
        d_c2[idx] = c_t[B_ * H_ + b * H_ + j];
    }
    // ---- initial tag logits (blocks 64..95, threads 0..127) ----
    if (row >= 64 && row < 96 && tid < 128) {
        int b = row - 64;                          // batch
        int k = tid;                               // tag
        const float* x  = hid + (size_t)b * T_ * D_;
        const float* wr = W_out + (size_t)k * H_;
        float a0 = 0.f, a1 = 0.f, a2 = 0.f, a3 = 0.f;
        for (int j = 0; j < H_; j += 4) {
            float4 w4 = *(const float4*)(wr + j);
            a0 += w4.x * x[j + 0];
            a1 += w4.y * x[j + 1];
            a2 += w4.z * x[j + 2];
            a3 += w4.w * x[j + 3];
        }
        d_logit0[k * LROW + ((b & 3) << 5) + (b >> 2)] =
            (a0 + a1) + (a2 + a3) + b_out[k];
    }
}

// reset barrier counter
__global__ void k_zero() {
    if (threadIdx.x == 0) g_count = 0;
}

// -------- pre-projection SGEMM: 128x64 tile, 4x8/thread, 4 CTAs/SM ----------
// C[m][n] = A[8192x1024] x W[2048x1152,:1024]^T. m = b*256+t.
// Thread (tid&31)=my covers rows m0+my*4..+3; (tid>>5)=wx covers cols n0+wx*8..+7.
__global__ void __launch_bounds__(256, 4) k_pre(const float* __restrict__ A,
                                                const float* __restrict__ W,
                                                const float* __restrict__ bih,
                                                const float* __restrict__ bhh) {
    __shared__ float As[16][132];
    __shared__ float Bs[16][68];
    int tid = threadIdx.x;
    int n0 = blockIdx.x * 64;
    int m0 = blockIdx.y * 128;
    int my = tid & 31;             // M sub-tile (4 rows each)
    int wx = tid >> 5;             // N sub-tile (8 cols each)
    // A staging: lr = tid>>1 (0..127 rows), lc = (tid&1)*8
    int lr = tid >> 1;
    int lc = (tid & 1) * 8;
    // B staging: rowB = tid&63, colB = (tid>>6)*4
    int rowB = tid & 63;
    int colB = (tid >> 6) * 4;

    unsigned long long acc2[4][4];
#pragma unroll
    for (int i = 0; i < 4; i++)
#pragma unroll
        for (int j = 0; j < 4; j++) acc2[i][j] = 0ull;

    for (int kt = 0; kt < D_; kt += 16) {
        float4 a0 = *(const float4*)&A[(size_t)(m0 + lr) * D_ + kt + lc];
        float4 a1 = *(const float4*)&A[(size_t)(m0 + lr) * D_ + kt + lc + 4];
        float4 b0 = *(const float4*)&W[(size_t)(n0 + rowB) * (D_ + K_) + kt + colB];
        As[lc + 0][lr] = a0.x; As[lc + 1][lr] = a0.y;
        As[lc + 2][lr] = a0.z; As[lc + 3][lr] = a0.w;
        As[lc + 4][lr] = a1.x; As[lc + 5][lr] = a1.y;
        As[lc + 6][lr] = a1.z; As[lc + 7][lr] = a1.w;
        Bs[colB + 0][rowB] = b0.x; Bs[colB + 1][rowB] = b0.y;
        Bs[colB + 2][rowB] = b0.z; Bs[colB + 3][rowB] = b0.w;
        __syncthreads();
#pragma unroll 16
        for (int k = 0; k < 16; k++) {
            float4 ra = *(const float4*)&As[k][my * 4];
            ulonglong2 wA = *(const ulonglong2*)&Bs[k][wx * 8];
            ulonglong2 wB = *(const ulonglong2*)&Bs[k][wx * 8 + 4];
            unsigned long long x0 = pk2(ra.x), x1 = pk2(ra.y);
            unsigned long long x2 = pk2(ra.z), x3 = pk2(ra.w);
            fma2(acc2[0][0], x0, wA.x); fma2(acc2[0][1], x0, wA.y);
            fma2(acc2[0][2], x0, wB.x); fma2(acc2[0][3], x0, wB.y);
            fma2(acc2[1][0], x1, wA.x); fma2(acc2[1][1], x1, wA.y);
            fma2(acc2[1][2], x1, wB.x); fma2(acc2[1][3], x1, wB.y);
            fma2(acc2[2][0], x2, wA.x); fma2(acc2[2][1], x2, wA.y);
            fma2(acc2[2][2], x2, wB.x); fma2(acc2[2][3], x2, wB.y);
            fma2(acc2[3][0], x3, wA.x); fma2(acc2[3][1], x3, wA.y);
            fma2(acc2[3][2], x3, wB.x); fma2(acc2[3][3], x3, wB.y);
        }
        __syncthreads();
    }

#pragma unroll
    for (int i = 0; i < 4; i++) {
        int m = m0 + my * 4 + i;
        int tt = m & 255;
        int bb = m >> 8;
#pragma unroll
        for (int j2 = 0; j2 < 4; j2++) {
            float lo, hi;
            unpk2(lo, hi, acc2[i][j2]);
            int nb = n0 + wx * 8 + j2 * 2;
            d_pre0[((size_t)tt * R_ + nb + 0) * B_ + bb] = lo + bih[nb] + bhh[nb];
            d_pre0[((size_t)tt * R_ + nb + 1) * B_ + bb] = hi + bih[nb + 1] + bhh[nb + 1];
        }
    }
}

// ------------------------- persistent recurrence (R9) ------------------------
__global__ void __launch_bounds__(512, 1) k_loop(const float* __restrict__ W_out,
                                                 const float* __restrict__ b_out) {
    extern __shared__ float smem[];
    float* w0s     = smem;                    // 640*16  = 10240
    float* w1s     = w0s + KC0 * 16;          // 1024*16 = 16384
    float* woutT   = w1s + KC1 * 16;          // [ul][k] 4*128 = 512
    float* bias1s  = woutT + 512;             // 16 (padded to 32)
    float* parthA  = bias1s + 32;             // 256*PS = 8704 (cell0 h partials)
    float* partB   = parthA + 256 * PS;       // 8704 (e / cell1 partials)
    float* zps     = partB + 256 * PS;        // 16*32 = 512
    float* rowH    = zps + 512;               // 16*PS = 544
    float* rowE    = rowH + 16 * PS;          // 544
    float* zs      = rowE + 16 * PS;          // 32
    float* h2s     = zs + 32;                 // 4*32 = 128

    const int c    = blockIdx.x;
    const int tid  = threadIdx.x;
    const int lane = tid & 31;
    const int w    = tid >> 5;                // 16 warps
    const int r_   = tid >> 5;                // row index for 512-thread reduce
    const int r4   = (lane >> 3) << 2;        // hybrid row-group base
    const int b4   = (lane & 7) << 2;         // hybrid batch base
    const int bo   = ((lane & 3) << 5) + (lane >> 2);  // interleaved logit offset

    // ---- stage weights into SMEM (once) ----
#pragma unroll
    for (int r = 0; r < 16; r++) {
        int grow = (r >> 2) * H_ + c * 4 + (r & 3);
        const float* src0 = d_W0 + (size_t)grow * KC0;
        for (int k = tid; k < KC0; k += 512) w0s[k * 16 + r] = src0[k];
        const float* src1 = d_W1 + (size_t)grow * KC1;
        for (int k = tid; k < KC1; k += 512) w1s[k * 16 + r] = src1[k];
        if (tid == 0) bias1s[r] = d_bias1[grow];
    }
    {   // W_out columns for this CTA's 4 units: woutT[ul*128 + k]
        int ul2 = tid >> 7, k2 = tid & 127;
        woutT[tid] = W_out[(size_t)k2 * H_ + c * 4 + ul2];
    }
    __syncthreads();

    // ---- per-thread cell state (tid<128): b = tid&31, ul = tid>>5 ----
    float c1_reg = 0.f, c2_reg = 0.f;
    int b = tid & 31, ul = tid >> 5;
    int u = c * 4 + (ul & 3);
    float pre[4];
    if (tid < 128) {
        c1_reg = d_c1[u * 32 + b];
        c2_reg = d_c2[u * 32 + b];
#pragma unroll
        for (int g = 0; g < 4; g++)
            pre[g] = __ldcg(&d_pre0[((size_t)0 * R_ + g * H_ + u) * B_ + b]);
    }

    // ---- prologue: cell0 h-part partials for t=0 (h1 buffer 0) ----
    {
        unsigned long long acc[4][2];
#pragma unroll
        for (int i = 0; i < 4; i++) { acc[i][0] = 0ull; acc[i][1] = 0ull; }
        dot32(acc, w0s + (w * 32) * 16, d_h1 + (w * 32) * 32, r4, b4);
        store_acc(parthA, w * 16, acc, r4, b4);
    }
    __syncthreads();

    unsigned tgt = G_;

    for (int t = 0; t < T_; t++) {
        const int old = t & 1, nw = old ^ 1;
        float*       __restrict__ h1new = d_h1 + nw  * (H_ * B_);
        const float* __restrict__ h2old = d_h2 + old * (H_ * B_);
        float*       __restrict__ h2new = d_h2 + nw  * (H_ * B_);

        // ======================= phase A: e-dot + gate0 ======================
        {
            unsigned long long acce[8];
#pragma unroll
            for (int p = 0; p < 8; p++) acce[p] = 0ull;
            const float* lg = (t == 0) ? d_logit0
                                       : d_logits + (size_t)(t - 1) * (K_ * LROW);
            float zp = 0.f;
            int ke0 = w * 8;
#pragma unroll
            for (int kk = 0; kk < 8; kk++) {
                float ev = __expf(__ldcg(lg + (ke0 + kk) * LROW + bo));
                zp += ev;
                unsigned long long xx = pk2(ev);
                const ulonglong2* q = (const ulonglong2*)(w0s + (H_ + ke0 + kk) * 16);
                ulonglong2 q0 = q[0], q1 = q[1], q2 = q[2], q3 = q[3];
                fma2(acce[0], xx, q0.x); fma2(acce[1], xx, q0.y);
                fma2(acce[2], xx, q1.x); fma2(acce[3], xx, q1.y);
                fma2(acce[4], xx, q2.x); fma2(acce[5], xx, q2.y);
                fma2(acce[6], xx, q3.x); fma2(acce[7], xx, q3.y);
            }
            zps[w * 32 + lane] = zp;
#pragma unroll
            for (int p = 0; p < 8; p++) {
                float lo, hi; unpk2(lo, hi, acce[p]);
                partB[(w * 16 + 2 * p + 0) * PS + lane] = lo;
                partB[(w * 16 + 2 * p + 1) * PS + lane] = hi;
            }
        }
        __syncthreads();

        // 512-thread parallel row reduction
        {
            float se = 0.f, sh = 0.f;
#pragma unroll
            for (int w2 = 0; w2 < 16; w2++) {
                se += partB[(w2 * 16 + r_) * PS + lane];
                sh += parthA[(w2 * 16 + r_) * PS + lane];
            }
            rowE[r_ * PS + lane] = se;
            rowH[r_ * PS + lane] = sh;
            if (tid < 32) {
                float z = 0.f;
#pragma unroll
                for (int w2 = 0; w2 < 16; w2++) z += zps[w2 * 32 + tid];
                zs[tid] = z;
            }
        }
        __syncthreads();

        if (tid < 128) {
            float invZ = __fdividef(1.0f, zs[b]);
            float gate[4];
#pragma unroll
            for (int g = 0; g < 4; g++) {
                int r = g * 4 + ul;
                gate[g] = pre[g] + rowH[r * PS + b] + rowE[r * PS + b] * invZ;
            }
            float iv = sigf(gate[0]);
            float fv = sigf(gate[1]);
            float gv = tanhfast(gate[2]);
            float ov = sigf(gate[3]);
            c1_reg = fv * c1_reg + iv * gv;
            h1new[u * 32 + b] = ov * tanhfast(c1_reg);
        }
        gbar_arrive();                          // bar1 arrive

        // ===== cell1 dot: h2-half (no h1 dependency) overlaps bar1 wait ======
        unsigned long long acc1[4][2];
#pragma unroll
        for (int i = 0; i < 4; i++) { acc1[i][0] = 0ull; acc1[i][1] = 0ull; }
        dot32(acc1, w1s + (H_ + w * 32) * 16, h2old + (w * 32) * 32, r4, b4);
        gbar_wait(tgt); tgt += G_;              // bar1 wait (h1[t] now global)

        // ======================= phase B: cell1 h1-half ======================
        dot32(acc1, w1s + (w * 32) * 16, h1new + (w * 32) * 32, r4, b4);
        store_acc(partB, w * 16, acc1, r4, b4);
        __syncthreads();

        {   // 512-thread row reduction
            float s = 0.f;
#pragma unroll
            for (int w2 = 0; w2 < 16; w2++) s += partB[(w2 * 16 + r_) * PS + lane];
            rowH[r_ * PS + lane] = s;
        }
        __syncthreads();

        if (tid < 128) {
            float gate[4];
#pragma unroll
            for (int g = 0; g < 4; g++) {
                int r = g * 4 + ul;
                gate[g] = bias1s[r] + rowH[r * PS + b];
            }
            float iv = sigf(gate[0]);
            float fv = sigf(gate[1]);
            float gv = tanhfast(gate[2]);
            float ov = sigf(gate[3]);
            c2_reg = fv * c2_reg + iv * gv;
            float h2v = ov * tanhfast(c2_reg);
            h2new[u * 32 + b] = h2v;
            h2s[(ul & 3) * 32 + b] = h2v;
        }
        __syncthreads();

        // scatter: warp w owns tags k = w*8..w*8+7; lane = batch (interleaved)
        {
            float h0 = h2s[lane];
            float h1v = h2s[32 + lane];
            float h2q = h2s[64 + lane];
            float h3 = h2s[96 + lane];
            float* dstl = d_logits + (size_t)t * (K_ * LROW);
            int k0 = w * 8;
#pragma unroll
            for (int kk = 0; kk < 8; kk++) {
                int kq = k0 + kk;
                float v = woutT[kq] * h0 + woutT[128 + kq] * h1v
                        + woutT[256 + kq] * h2q + woutT[384 + kq] * h3;
                atomicAdd(dstl + kq * LROW + bo, v);
            }
        }
        // prefetch pre0 for next step
        if (tid < 128) {
            int tn = (t + 1 < T_) ? (t + 1) : t;
#pragma unroll
            for (int g = 0; g < 4; g++)
                pre[g] = __ldcg(&d_pre0[((size_t)tn * R_ + g * H_ + u) * B_ + b]);
        }
        gbar_arrive();                          // bar2 arrive

        // ==== cell0 h-part dot for step t+1 (uses h1[t]) overlaps bar2 =======
        {
            unsigned long long acc[4][2];
#pragma unroll
            for (int i = 0; i < 4; i++) { acc[i][0] = 0ull; acc[i][1] = 0ull; }
            dot32(acc, w0s + (w * 32) * 16, h1new + (w * 32) * 32, r4, b4);
            store_acc(parthA, w * 16, acc, r4, b4);
        }
        __syncthreads();
        gbar_wait(tgt); tgt += G_;              // bar2 wait (logits[t] global)
    }
}

// --------------------------- final masked softmax ----------------------------
__global__ void __launch_bounds__(256) k_final(const float* __restrict__ mask,
                                               float* __restrict__ out) {
    int tid = threadIdx.x, lane = tid & 31, w = tid >> 5;
    int gidx = blockIdx.x * 8 + w;             // 0..8191
    int b = gidx >> 8, t = gidx & 255;
    float pen = (1.0f - mask[b * T_ + t]) * -1e32f;
    int bo = ((b & 3) << 5) + (b >> 2);
    float v[4];
#pragma unroll
    for (int i = 0; i < 4; i++)
        v[i] = d_logits[(size_t)t * (K_ * LROW) + (lane + 32 * i) * LROW + bo] + pen;
    float mx = fmaxf(fmaxf(v[0], v[1]), fmaxf(v[2], v[3]));
#pragma unroll
    for (int o = 16; o > 0; o >>= 1) mx = fmaxf(mx, __shfl_xor_sync(~0u, mx, o));
    float s = 0.f;
#pragma unroll
    for (int i = 0; i < 4; i++) { v[i] = __expf(v[i] - mx); s += v[i]; }
#pragma unroll
    for (int o = 16; o > 0; o >>= 1) s += __shfl_xor_sync(~0u, s, o);
    float inv = 1.0f / s;
#pragma unroll
    for (int i = 0; i < 4; i++)
        out[((size_t)b * T_ + t) * K_ + lane + 32 * i] = v[i] * inv;
}

// ----------------------------------------------------------------------------
extern "C" void kernel_launch(void* const* d_in, const int* in_sizes, int n_in,
                              void* d_out, int out_size) {
    const float* hiddens = (const float*)d_in[0];
    const float* h_t     = (const float*)d_in[1];
    const float* c_t     = (const float*)d_in[2];
    const float* mask    = (const float*)d_in[3];
    const float* W_out   = (const float*)d_in[4];
    const float* b_out   = (const float*)d_in[5];
    const float* W_ih0   = (const float*)d_in[6];
    const float* W_hh0   = (const float*)d_in[7];
    const float* b_ih0   = (const float*)d_in[8];
    const float* b_hh0   = (const float*)d_in[9];
    const float* W_ih1   = (const float*)d_in[10];
    const float* W_hh1   = (const float*)d_in[11];
    const float* b_ih1   = (const float*)d_in[12];
    const float* b_hh1   = (const float*)d_in[13];
    float* out = (float*)d_out;

    // loop SMEM floats: 10240+16384+512+32 + 8704 + 8704 + 512 + 544 + 544
    //                 + 32 + 128 = 46336 floats = 185344 bytes
    const int SMEM_LOOP = 46336 * 4;
    cudaFuncSetAttribute(k_loop, cudaFuncAttributeMaxDynamicSharedMemorySize, SMEM_LOOP);

    k_setup<<<R_, 256>>>(W_ih0, W_hh0, W_ih1, W_hh1, b_ih1, b_hh1,
                         h_t, c_t, hiddens, W_out, b_out);
    k_pre<<<dim3(32, 64), 256>>>(hiddens, W_ih0, b_ih0, b_hh0);
    k_zero<<<1, 32>>>();
    k_loop<<<G_, 512, SMEM_LOOP>>>(W_out, b_out);
    k_final<<<1024, 256>>>(mask, out);
}

// round 14
// speedup vs baseline: 1.2751x; 1.1350x over previous
#include <cuda_runtime.h>
#include <cuda_bf16.h>
#include <cstdint>
#include <cstddef>

// ---------------------------------------------------------------------------
// TaggingFNNDecoder: 2-layer LSTM tag decoder. B=32, T=256, D=1024, H=512, K=128
// Round 13: loop = R9 best (untouched). k_pre = bf16-split-3 GEMM via
// mma.sync.m16n8k16 (baseline PTX HMMA; tcgen05 blocked by compute_103 target).
// ---------------------------------------------------------------------------

#define B_  32
#define T_  256
#define D_  1024
#define H_  512
#define K_  128
#define R_  2048    // 4*H gate rows
#define KC0 640     // cell0 reduced k-dim: h1(512) + e(128)
#define KC1 1024    // cell1 k-dim: h1(512) + h2(512)
#define G_  128     // persistent grid size (1 CTA/SM)
#define PS  34      // padded row stride for partial arrays (8B-aligned pairs)
#define LROW 128    // interleaved logits row stride (floats per tag)

// ------------------------- device scratch ----------------------------------
__device__ float d_pre0[(size_t)T_ * R_ * B_];   // 64 MB [t][row][b]
__device__ float d_W0[(size_t)R_ * KC0];         // [row][ W_hh0 | W_ih0[:,1024:] ]
__device__ float d_W1[(size_t)R_ * KC1];         // [row][ W_ih1 | W_hh1 ]
__device__ float d_bias1[R_];
__device__ float d_h1[2 * H_ * B_];              // double buffered [j][b]
__device__ float d_h2[2 * H_ * B_];
__device__ float d_c1[H_ * B_];
__device__ float d_c2[H_ * B_];
__device__ float d_logit0[K_ * LROW];            // interleaved initial logits
__device__ float d_logits[(size_t)T_ * K_ * LROW]; // interleaved raw logits

// bf16 split operands for the HMMA pre-projection GEMM
__device__ __nv_bfloat16 d_Ahi[(size_t)8192 * 1024];   // 16 MB
__device__ __nv_bfloat16 d_Alo[(size_t)8192 * 1024];   // 16 MB
__device__ __nv_bfloat16 d_Whi[(size_t)R_ * 1024];     // 4 MB
__device__ __nv_bfloat16 d_Wlo[(size_t)R_ * 1024];     // 4 MB

// central barrier counter (monotonic within one launch; reset by k_zero)
__device__ unsigned g_count;

// fast NaN-free activations
__device__ __forceinline__ float sigf(float x) {
    return __fdividef(1.0f, 1.0f + __expf(-x));
}
__device__ __forceinline__ float tanhfast(float x) {
    return 1.0f - __fdividef(2.0f, 1.0f + __expf(2.0f * x));
}

// packed fp32x2 helpers
__device__ __forceinline__ unsigned long long pk2(float x) {
    unsigned long long r; unsigned u = __float_as_uint(x);
    asm("mov.b64 %0, {%1, %1};" : "=l"(r) : "r"(u));
    return r;
}
__device__ __forceinline__ void fma2(unsigned long long& a,
                                     unsigned long long x, unsigned long long w) {
    asm("fma.rn.f32x2 %0, %1, %2, %0;" : "+l"(a) : "l"(x), "l"(w));
}
__device__ __forceinline__ void unpk2(float& lo, float& hi, unsigned long long v) {
    unsigned l, h;
    asm("mov.b64 {%0, %1}, %2;" : "=r"(l), "=r"(h) : "l"(v));
    lo = __uint_as_float(l); hi = __uint_as_float(h);
}

// split grid barrier
__device__ __forceinline__ void gbar_arrive() {
    __syncthreads();
    if (threadIdx.x == 0) {
        asm volatile("red.release.gpu.add.u32 [%0], %1;"
                     :: "l"(&g_count), "r"(1u) : "memory");
    }
}
__device__ __forceinline__ void gbar_wait(unsigned target) {
    if (threadIdx.x == 0) {
        unsigned v;
        do {
            asm volatile("ld.acquire.gpu.u32 %0, [%1];"
                         : "=r"(v) : "l"(&g_count) : "memory");
        } while ((int)(v - target) < 0);
    }
    __syncthreads();
}

// hybrid dot body (R9)
__device__ __forceinline__ void dot32(unsigned long long acc[4][2],
                                      const float* __restrict__ wbase,
                                      const float* __restrict__ xsrc,
                                      int r4, int b4) {
#pragma unroll 8
    for (int kk = 0; kk < 32; kk++) {
        float4 wv = *(const float4*)(wbase + kk * 16 + r4);
        unsigned long long x01, x23;
        asm("ld.global.cg.v2.b64 {%0,%1}, [%2];"
            : "=l"(x01), "=l"(x23) : "l"(xsrc + kk * 32 + b4));
        unsigned long long w0p = pk2(wv.x), w1p = pk2(wv.y);
        unsigned long long w2p = pk2(wv.z), w3p = pk2(wv.w);
        fma2(acc[0][0], x01, w0p); fma2(acc[0][1], x23, w0p);
        fma2(acc[1][0], x01, w1p); fma2(acc[1][1], x23, w1p);
        fma2(acc[2][0], x01, w2p); fma2(acc[2][1], x23, w2p);
        fma2(acc[3][0], x01, w3p); fma2(acc[3][1], x23, w3p);
    }
}

__device__ __forceinline__ void store_acc(float* part, int wbase_row,
                                          unsigned long long acc[4][2],
                                          int r4, int b4) {
#pragma unroll
    for (int rr = 0; rr < 4; rr++) {
        unsigned long long* p =
            (unsigned long long*)(part + (wbase_row + r4 + rr) * PS + b4);
        p[0] = acc[rr][0];
        p[1] = acc[rr][1];
    }
}

// -------------------- setup: pack weights + init states + bf16 split --------
__global__ void k_setup(const float* __restrict__ Wih0, const float* __restrict__ Whh0,
                        const float* __restrict__ Wih1, const float* __restrict__ Whh1,
                        const float* __restrict__ bih1, const float* __restrict__ bhh1,
                        const float* __restrict__ h_t,  const float* __restrict__ c_t,
                        const float* __restrict__ hid,  const float* __restrict__ W_out,
                        const float* __restrict__ b_out) {
    int row = blockIdx.x;          // 0..2047
    int tid = threadIdx.x;         // 256 threads
    // ---- weight pack (loop weights) ----
    const float4* s1 = (const float4*)(Whh0 + (size_t)row * H_);
    float4* dW0 = (float4*)(d_W0 + (size_t)row * KC0);
    for (int i = tid; i < H_ / 4; i += 256) dW0[i] = s1[i];
    const float4* s2 = (const float4*)(Wih0 + (size_t)row * (D_ + K_) + D_);
    for (int i = tid; i < K_ / 4; i += 256) dW0[H_ / 4 + i] = s2[i];
    float4* dW1 = (float4*)(d_W1 + (size_t)row * KC1);
    const float4* s3 = (const float4*)(Wih1 + (size_t)row * H_);
    const float4* s4 = (const float4*)(Whh1 + (size_t)row * H_);
    for (int i = tid; i < H_ / 4; i += 256) { dW1[i] = s3[i]; dW1[H_ / 4 + i] = s4[i]; }
    if (tid == 0) d_bias1[row] = bih1[row] + bhh1[row];

    // ---- bf16 split of W_ih0[:, :1024] (GEMM B operand) ----
    for (int k = tid; k < 1024; k += 256) {
        float v = Wih0[(size_t)row * (D_ + K_) + k];
        __nv_bfloat16 hv = __float2bfloat16(v);
        d_Whi[(size_t)row * 1024 + k] = hv;
        d_Wlo[(size_t)row * 1024 + k] = __float2bfloat16(v - __bfloat162float(hv));
    }
    // ---- bf16 split of hiddens (GEMM A operand); 4096 elems per block ----
    {
        size_t base = (size_t)row * 4096;
        for (int i = tid; i < 4096; i += 256) {
            float v = hid[base + i];
            __nv_bfloat16 hv = __float2bfloat16(v);
            d_Ahi[base + i] = hv;
            d_Alo[base + i] = __float2bfloat16(v - __bfloat162float(hv));
        }
    }

    // ---- logits prefill with output bias (blocks 0..255 <-> t) ----
    if (row < 256) {
        float* dst = d_logits + (size_t)row * K_ * LROW;
        for (int i = tid; i < K_ * LROW; i += 256) dst[i] = b_out[i >> 7];
    }
    // ---- state transpose (blocks 0..63) ----
    if (row < 64) {
        int idx = row * 256 + tid;                 // 0..16383 = j*32+b
        int j = idx >> 5, b = idx & 31;
        d_h1[idx] = h_t[b * H_ + j];
        d_h2[idx] = h_t[B_ * H_ + b * H_ + j];
        d_c1[idx] = c_t[b * H_ + j];
        d_c2[idx] = c_t[B_ * H_ + b * H_ + j];
    }
    // ---- initial tag logits (blocks 64..95, threads 0..127) ----
    if (row >= 64 && row < 96 && tid < 128) {
        int b = row - 64;
        int k = tid;
        const float* x  = hid + (size_t)b * T_ * D_;
        const float* wr = W_out + (size_t)k * H_;
        float a0 = 0.f, a1 = 0.f, a2 = 0.f, a3 = 0.f;
        for (int j = 0; j < H_; j += 4) {
            float4 w4 = *(const float4*)(wr + j);
            a0 += w4.x * x[j + 0];
            a1 += w4.y * x[j + 1];
            a2 += w4.z * x[j + 2];
            a3 += w4.w * x[j + 3];
        }
        d_logit0[k * LROW + ((b & 3) << 5) + (b >> 2)] =
            (a0 + a1) + (a2 + a3) + b_out[k];
    }
}

// reset barrier counter
__global__ void k_zero() {
    if (threadIdx.x == 0) g_count = 0;
}

// ----------------------- mma.sync k_pre helpers ------------------------------
#define SMEM_SWZ(off) ((off) ^ (((off) >> 3) & 0x70))

__device__ __forceinline__ uint32_t smem_u32(const void* p) {
    uint32_t a;
    asm("{ .reg .u64 t; cvta.to.shared.u64 t, %1; cvt.u32.u64 %0, t; }"
        : "=r"(a) : "l"(p));
    return a;
}
__device__ __forceinline__ void lda4(uint32_t a[4], uint32_t addr) {
    asm volatile("ldmatrix.sync.aligned.m8n8.x4.shared.b16 {%0,%1,%2,%3}, [%4];"
                 : "=r"(a[0]), "=r"(a[1]), "=r"(a[2]), "=r"(a[3]) : "r"(addr));
}
__device__ __forceinline__ void ldb2(uint32_t b[2], uint32_t addr) {
    asm volatile("ldmatrix.sync.aligned.m8n8.x2.shared.b16 {%0,%1}, [%2];"
                 : "=r"(b[0]), "=r"(b[1]) : "r"(addr));
}
__device__ __forceinline__ void mma16816(float c[4], const uint32_t a[4],
                                         const uint32_t b[2]) {
    asm volatile(
        "mma.sync.aligned.m16n8k16.row.col.f32.bf16.bf16.f32 "
        "{%0,%1,%2,%3}, {%4,%5,%6,%7}, {%8,%9}, {%0,%1,%2,%3};"
        : "+f"(c[0]), "+f"(c[1]), "+f"(c[2]), "+f"(c[3])
        : "r"(a[0]), "r"(a[1]), "r"(a[2]), "r"(a[3]), "r"(b[0]), "r"(b[1]));
}

// -------- pre-projection GEMM: C[8192m x 2048n] = A x W^T, bf16-split-3 -----
// CTA tile 128m x 64n, 256 thr (8 warps, warp tile 32x32). K chunks of 64.
// SMEM: Ahi 16K | Alo 16K | Bhi 8K | Blo 8K = 48K (SW128 swizzled 128B rows).
#define SMP_AHI 0
#define SMP_ALO 16384
#define SMP_BHI 32768
#define SMP_BLO 40960
#define SMP_TOTAL 49152
__global__ void __launch_bounds__(256) k_preH(const float* __restrict__ bih,
                                              const float* __restrict__ bhh) {
    extern __shared__ char smem[];
    uint32_t sb = smem_u32(smem);
    int tid = threadIdx.x;
    int lane = tid & 31, w = tid >> 5;
    int n0 = blockIdx.x * 64;
    int m0 = blockIdx.y * 128;
    int wmbase = (w >> 1) * 32;    // 0,32,64,96
    int wnbase = (w & 1) * 32;     // 0,32

    // staging indices
    int am = tid >> 1, ah = tid & 1;

    // ldmatrix lane addressing (byte offsets within operand region)
    // A (x4): row = base + mt*16 + (lane&15), kunit = ks*2 + (lane>>4)
    int aRowL = lane & 15;
    int aKL   = lane >> 4;         // 0 or 1 (which k8 within k16)
    // B (x2): row = base + nt*8 + (lane&7), kunit = ks*2 + ((lane>>3)&1)
    int bRowL = lane & 7;
    int bKL   = (lane >> 3) & 1;

    float c[2][4][4];
#pragma unroll
    for (int mt = 0; mt < 2; mt++)
#pragma unroll
        for (int nt = 0; nt < 4; nt++)
#pragma unroll
            for (int i = 0; i < 4; i++) c[mt][nt][i] = 0.f;

    for (int kc = 0; kc < 16; kc++) {
        // ---- stage chunk into swizzled SMEM ----
        {
            const uint4* gh = (const uint4*)(d_Ahi + (size_t)(m0 + am) * 1024 + kc * 64 + ah * 32);
            const uint4* gl = (const uint4*)(d_Alo + (size_t)(m0 + am) * 1024 + kc * 64 + ah * 32);
#pragma unroll
            for (int g = 0; g < 4; g++) {
                uint32_t off = SMEM_SWZ((uint32_t)(am * 128 + (ah * 4 + g) * 16));
                *(uint4*)(smem + SMP_AHI + off) = gh[g];
                *(uint4*)(smem + SMP_ALO + off) = gl[g];
            }
#pragma unroll
            for (int i2 = 0; i2 < 2; i2++) {
                int i = tid * 2 + i2;              // 0..511
                int rowB = i >> 3, g = i & 7;
                const uint4* bh = (const uint4*)(d_Whi + (size_t)(n0 + rowB) * 1024 + kc * 64 + g * 8);
                const uint4* bl = (const uint4*)(d_Wlo + (size_t)(n0 + rowB) * 1024 + kc * 64 + g * 8);
                uint32_t off = SMEM_SWZ((uint32_t)(rowB * 128 + g * 16));
                *(uint4*)(smem + SMP_BHI + off) = bh[0];
                *(uint4*)(smem + SMP_BLO + off) = bl[0];
            }
        }
        __syncthreads();

#pragma unroll
        for (int ks = 0; ks < 4; ks++) {
            uint32_t aHi[2][4], aLo[2][4];
#pragma unroll
            for (int mt = 0; mt < 2; mt++) {
                int row = wmbase + mt * 16 + aRowL;
                uint32_t off = (uint32_t)(row * 128
                              + (((ks * 2 + aKL) * 16) ^ ((row & 7) << 4)));
                lda4(aHi[mt], sb + SMP_AHI + off);
                lda4(aLo[mt], sb + SMP_ALO + off);
            }
#pragma unroll
            for (int nt = 0; nt < 4; nt++) {
                uint32_t bHi[2], bLo[2];
                int row = wnbase + nt * 8 + bRowL;
                uint32_t off = (uint32_t)(row * 128
                              + (((ks * 2 + bKL) * 16) ^ ((row & 7) << 4)));
                ldb2(bHi, sb + SMP_BHI + off);
                ldb2(bLo, sb + SMP_BLO + off);
#pragma unroll
                for (int mt = 0; mt < 2; mt++) {
                    mma16816(c[mt][nt], aHi[mt], bHi);
                    mma16816(c[mt][nt], aHi[mt], bLo);
                    mma16816(c[mt][nt], aLo[mt], bHi);
                }
            }
        }
        __syncthreads();
    }

    // ---- epilogue: scatter into d_pre0[t][row][b] with bias ----
#pragma unroll
    for (int mt = 0; mt < 2; mt++) {
        int m = m0 + wmbase + mt * 16 + (lane >> 2);
        int tt = m & 255, bb = m >> 8;
        int tt8 = (m + 8) & 255;               // row+8 stays in same 128-block
#pragma unroll
        for (int nt = 0; nt < 4; nt++) {
            int nc = n0 + wnbase + nt * 8 + 2 * (lane & 3);
            float bz0 = bih[nc] + bhh[nc];
            float bz1 = bih[nc + 1] + bhh[nc + 1];
            d_pre0[((size_t)tt  * R_ + nc)     * B_ + bb] = c[mt][nt][0] + bz0;
            d_pre0[((size_t)tt  * R_ + nc + 1) * B_ + bb] = c[mt][nt][1] + bz1;
            d_pre0[((size_t)tt8 * R_ + nc)     * B_ + bb] = c[mt][nt][2] + bz0;
            d_pre0[((size_t)tt8 * R_ + nc + 1) * B_ + bb] = c[mt][nt][3] + bz1;
        }
    }
}

// ------------------------- persistent recurrence (R9) ------------------------
__global__ void __launch_bounds__(512, 1) k_loop(const float* __restrict__ W_out,
                                                 const float* __restrict__ b_out) {
    extern __shared__ float smemf[];
    float* w0s     = smemf;
    float* w1s     = w0s + KC0 * 16;
    float* woutT   = w1s + KC1 * 16;
    float* bias1s  = woutT + 512;
    float* parthA  = bias1s + 32;
    float* partB   = parthA + 256 * PS;
    float* zps     = partB + 256 * PS;
    float* rowH    = zps + 512;
    float* rowE    = rowH + 16 * PS;
    float* zs      = rowE + 16 * PS;
    float* h2s     = zs + 32;

    const int c    = blockIdx.x;
    const int tid  = threadIdx.x;
    const int lane = tid & 31;
    const int w    = tid >> 5;
    const int r_   = tid >> 5;
    const int r4   = (lane >> 3) << 2;
    const int b4   = (lane & 7) << 2;
    const int bo   = ((lane & 3) << 5) + (lane >> 2);

#pragma unroll
    for (int r = 0; r < 16; r++) {
        int grow = (r >> 2) * H_ + c * 4 + (r & 3);
        const float* src0 = d_W0 + (size_t)grow * KC0;
        for (int k = tid; k < KC0; k += 512) w0s[k * 16 + r] = src0[k];
        const float* src1 = d_W1 + (size_t)grow * KC1;
        for (int k = tid; k < KC1; k += 512) w1s[k * 16 + r] = src1[k];
        if (tid == 0) bias1s[r] = d_bias1[grow];
    }
    {
        int ul2 = tid >> 7, k2 = tid & 127;
        woutT[tid] = W_out[(size_t)k2 * H_ + c * 4 + ul2];
    }
    __syncthreads();

    float c1_reg = 0.f, c2_reg = 0.f;
    int b = tid & 31, ul = tid >> 5;
    int u = c * 4 + (ul & 3);
    float pre[4];
    if (tid < 128) {
        c1_reg = d_c1[u * 32 + b];
        c2_reg = d_c2[u * 32 + b];
#pragma unroll
        for (int g = 0; g < 4; g++)
            pre[g] = __ldcg(&d_pre0[((size_t)0 * R_ + g * H_ + u) * B_ + b]);
    }

    {
        unsigned long long acc[4][2];
#pragma unroll
        for (int i = 0; i < 4; i++) { acc[i][0] = 0ull; acc[i][1] = 0ull; }
        dot32(acc, w0s + (w * 32) * 16, d_h1 + (w * 32) * 32, r4, b4);
        store_acc(parthA, w * 16, acc, r4, b4);
    }
    __syncthreads();

    unsigned tgt = G_;

    for (int t = 0; t < T_; t++) {
        const int old = t & 1, nw = old ^ 1;
        float*       __restrict__ h1new = d_h1 + nw  * (H_ * B_);
        const float* __restrict__ h2old = d_h2 + old * (H_ * B_);
        float*       __restrict__ h2new = d_h2 + nw  * (H_ * B_);

        {
            unsigned long long acce[8];
#pragma unroll
            for (int p = 0; p < 8; p++) acce[p] = 0ull;
            const float* lg = (t == 0) ? d_logit0
                                       : d_logits + (size_t)(t - 1) * (K_ * LROW);
            float zp = 0.f;
            int ke0 = w * 8;
#pragma unroll
            for (int kk = 0; kk < 8; kk++) {
                float ev = __expf(__ldcg(lg + (ke0 + kk) * LROW + bo));
                zp += ev;
                unsigned long long xx = pk2(ev);
                const ulonglong2* q = (const ulonglong2*)(w0s + (H_ + ke0 + kk) * 16);
                ulonglong2 q0 = q[0], q1 = q[1], q2 = q[2], q3 = q[3];
                fma2(acce[0], xx, q0.x); fma2(acce[1], xx, q0.y);
                fma2(acce[2], xx, q1.x); fma2(acce[3], xx, q1.y);
                fma2(acce[4], xx, q2.x); fma2(acce[5], xx, q2.y);
                fma2(acce[6], xx, q3.x); fma2(acce[7], xx, q3.y);
            }
            zps[w * 32 + lane] = zp;
#pragma unroll
            for (int p = 0; p < 8; p++) {
                float lo, hi; unpk2(lo, hi, acce[p]);
                partB[(w * 16 + 2 * p + 0) * PS + lane] = lo;
                partB[(w * 16 + 2 * p + 1) * PS + lane] = hi;
            }
        }
        __syncthreads();

        {
            float se = 0.f, sh = 0.f;
#pragma unroll
            for (int w2 = 0; w2 < 16; w2++) {
                se += partB[(w2 * 16 + r_) * PS + lane];
                sh += parthA[(w2 * 16 + r_) * PS + lane];
            }
            rowE[r_ * PS + lane] = se;
            rowH[r_ * PS + lane] = sh;
            if (tid < 32) {
                float z = 0.f;
#pragma unroll
                for (int w2 = 0; w2 < 16; w2++) z += zps[w2 * 32 + tid];
                zs[tid] = z;
            }
        }
        __syncthreads();

        if (tid < 128) {
            float invZ = __fdividef(1.0f, zs[b]);
            float gate[4];
#pragma unroll
            for (int g = 0; g < 4; g++) {
                int r = g * 4 + ul;
                gate[g] = pre[g] + rowH[r * PS + b] + rowE[r * PS + b] * invZ;
            }
            float iv = sigf(gate[0]);
            float fv = sigf(gate[1]);
            float gv = tanhfast(gate[2]);
            float ov = sigf(gate[3]);
            c1_reg = fv * c1_reg + iv * gv;
            h1new[u * 32 + b] = ov * tanhfast(c1_reg);
        }
        gbar_arrive();

        unsigned long long acc1[4][2];
#pragma unroll
        for (int i = 0; i < 4; i++) { acc1[i][0] = 0ull; acc1[i][1] = 0ull; }
        dot32(acc1, w1s + (H_ + w * 32) * 16, h2old + (w * 32) * 32, r4, b4);
        gbar_wait(tgt); tgt += G_;

        dot32(acc1, w1s + (w * 32) * 16, h1new + (w * 32) * 32, r4, b4);
        store_acc(partB, w * 16, acc1, r4, b4);
        __syncthreads();

        {
            float s = 0.f;
#pragma unroll
            for (int w2 = 0; w2 < 16; w2++) s += partB[(w2 * 16 + r_) * PS + lane];
            rowH[r_ * PS + lane] = s;
        }
        __syncthreads();

        if (tid < 128) {
            float gate[4];
#pragma unroll
            for (int g = 0; g < 4; g++) {
                int r = g * 4 + ul;
                gate[g] = bias1s[r] + rowH[r * PS + b];
            }
            float iv = sigf(gate[0]);
            float fv = sigf(gate[1]);
            float gv = tanhfast(gate[2]);
            float ov = sigf(gate[3]);
            c2_reg = fv * c2_reg + iv * gv;
            float h2v = ov * tanhfast(c2_reg);
            h2new[u * 32 + b] = h2v;
            h2s[(ul & 3) * 32 + b] = h2v;
        }
        __syncthreads();

        {
            float h0 = h2s[lane];
            float h1v = h2s[32 + lane];
            float h2q = h2s[64 + lane];
            float h3 = h2s[96 + lane];
            float* dstl = d_logits + (size_t)t * (K_ * LROW);
            int k0 = w * 8;
#pragma unroll
            for (int kk = 0; kk < 8; kk++) {
                int kq = k0 + kk;
                float v = woutT[kq] * h0 + woutT[128 + kq] * h1v
                        + woutT[256 + kq] * h2q + woutT[384 + kq] * h3;
                atomicAdd(dstl + kq * LROW + bo, v);
            }
        }
        if (tid < 128) {
            int tn = (t + 1 < T_) ? (t + 1) : t;
#pragma unroll
            for (int g = 0; g < 4; g++)
                pre[g] = __ldcg(&d_pre0[((size_t)tn * R_ + g * H_ + u) * B_ + b]);
        }
        gbar_arrive();

        {
            unsigned long long acc[4][2];
#pragma unroll
            for (int i = 0; i < 4; i++) { acc[i][0] = 0ull; acc[i][1] = 0ull; }
            dot32(acc, w0s + (w * 32) * 16, h1new + (w * 32) * 32, r4, b4);
            store_acc(parthA, w * 16, acc, r4, b4);
        }
        __syncthreads();
        gbar_wait(tgt); tgt += G_;
    }
}

// --------------------------- final masked softmax ----------------------------
__global__ void __launch_bounds__(256) k_final(const float* __restrict__ mask,
                                               float* __restrict__ out) {
    int tid = threadIdx.x, lane = tid & 31, w = tid >> 5;
    int gidx = blockIdx.x * 8 + w;
    int b = gidx >> 8, t = gidx & 255;
    float pen = (1.0f - mask[b * T_ + t]) * -1e32f;
    int bo = ((b & 3) << 5) + (b >> 2);
    float v[4];
#pragma unroll
    for (int i = 0; i < 4; i++)
        v[i] = d_logits[(size_t)t * (K_ * LROW) + (lane + 32 * i) * LROW + bo] + pen;
    float mx = fmaxf(fmaxf(v[0], v[1]), fmaxf(v[2], v[3]));
#pragma unroll
    for (int o = 16; o > 0; o >>= 1) mx = fmaxf(mx, __shfl_xor_sync(~0u, mx, o));
    float s = 0.f;
#pragma unroll
    for (int i = 0; i < 4; i++) { v[i] = __expf(v[i] - mx); s += v[i]; }
#pragma unroll
    for (int o = 16; o > 0; o >>= 1) s += __shfl_xor_sync(~0u, s, o);
    float inv = 1.0f / s;
#pragma unroll
    for (int i = 0; i < 4; i++)
        out[((size_t)b * T_ + t) * K_ + lane + 32 * i] = v[i] * inv;
}

// ----------------------------------------------------------------------------
extern "C" void kernel_launch(void* const* d_in, const int* in_sizes, int n_in,
                              void* d_out, int out_size) {
    const float* hiddens = (const float*)d_in[0];
    const float* h_t     = (const float*)d_in[1];
    const float* c_t     = (const float*)d_in[2];
    const float* mask    = (const float*)d_in[3];
    const float* W_out   = (const float*)d_in[4];
    const float* b_out   = (const float*)d_in[5];
    const float* W_ih0   = (const float*)d_in[6];
    const float* W_hh0   = (const float*)d_in[7];
    const float* b_ih0   = (const float*)d_in[8];
    const float* b_hh0   = (const float*)d_in[9];
    const float* W_ih1   = (const float*)d_in[10];
    const float* W_hh1   = (const float*)d_in[11];
    const float* b_ih1   = (const float*)d_in[12];
    const float* b_hh1   = (const float*)d_in[13];
    float* out = (float*)d_out;

    const int SMEM_LOOP = 46336 * 4;   // same as R9
    cudaFuncSetAttribute(k_loop, cudaFuncAttributeMaxDynamicSharedMemorySize, SMEM_LOOP);
    cudaFuncSetAttribute(k_preH, cudaFuncAttributeMaxDynamicSharedMemorySize, SMP_TOTAL);

    k_setup<<<R_, 256>>>(W_ih0, W_hh0, W_ih1, W_hh1, b_ih1, b_hh1,
                         h_t, c_t, hiddens, W_out, b_out);
    k_preH<<<dim3(32, 64), 256, SMP_TOTAL>>>(b_ih0, b_hh0);
    k_zero<<<1, 32>>>();
    k_loop<<<G_, 512, SMEM_LOOP>>>(W_out, b_out);
    k_final<<<1024, 256>>>(mask, out);
}

// round 15
// speedup vs baseline: 1.2860x; 1.0086x over previous
#include <cuda_runtime.h>
#include <cuda_bf16.h>
#include <cstdint>
#include <cstddef>

// ---------------------------------------------------------------------------
// TaggingFNNDecoder: 2-layer LSTM tag decoder. B=32, T=256, D=1024, H=512, K=128
// Round 14: R13 + h-part row reduction moved off the phase-A critical path
// into the bar2 window (rowHA computed at end of step t for step t+1).
// k_pre = bf16-split-3 HMMA GEMM (R13, unchanged).
// ---------------------------------------------------------------------------

#define B_  32
#define T_  256
#define D_  1024
#define H_  512
#define K_  128
#define R_  2048    // 4*H gate rows
#define KC0 640     // cell0 reduced k-dim: h1(512) + e(128)
#define KC1 1024    // cell1 k-dim: h1(512) + h2(512)
#define G_  128     // persistent grid size (1 CTA/SM)
#define PS  34      // padded row stride for partial arrays (8B-aligned pairs)
#define LROW 128    // interleaved logits row stride (floats per tag)

// ------------------------- device scratch ----------------------------------
__device__ float d_pre0[(size_t)T_ * R_ * B_];   // 64 MB [t][row][b]
__device__ float d_W0[(size_t)R_ * KC0];         // [row][ W_hh0 | W_ih0[:,1024:] ]
__device__ float d_W1[(size_t)R_ * KC1];         // [row][ W_ih1 | W_hh1 ]
__device__ float d_bias1[R_];
__device__ float d_h1[2 * H_ * B_];              // double buffered [j][b]
__device__ float d_h2[2 * H_ * B_];
__device__ float d_c1[H_ * B_];
__device__ float d_c2[H_ * B_];
__device__ float d_logit0[K_ * LROW];            // interleaved initial logits
__device__ float d_logits[(size_t)T_ * K_ * LROW]; // interleaved raw logits

// bf16 split operands for the HMMA pre-projection GEMM
__device__ __nv_bfloat16 d_Ahi[(size_t)8192 * 1024];   // 16 MB
__device__ __nv_bfloat16 d_Alo[(size_t)8192 * 1024];   // 16 MB
__device__ __nv_bfloat16 d_Whi[(size_t)R_ * 1024];     // 4 MB
__device__ __nv_bfloat16 d_Wlo[(size_t)R_ * 1024];     // 4 MB

// central barrier counter (monotonic within one launch; reset by k_zero)
__device__ unsigned g_count;

// fast NaN-free activations
__device__ __forceinline__ float sigf(float x) {
    return __fdividef(1.0f, 1.0f + __expf(-x));
}
__device__ __forceinline__ float tanhfast(float x) {
    return 1.0f - __fdividef(2.0f, 1.0f + __expf(2.0f * x));
}

// packed fp32x2 helpers
__device__ __forceinline__ unsigned long long pk2(float x) {
    unsigned long long r; unsigned u = __float_as_uint(x);
    asm("mov.b64 %0, {%1, %1};" : "=l"(r) : "r"(u));
    return r;
}
__device__ __forceinline__ void fma2(unsigned long long& a,
                                     unsigned long long x, unsigned long long w) {
    asm("fma.rn.f32x2 %0, %1, %2, %0;" : "+l"(a) : "l"(x), "l"(w));
}
__device__ __forceinline__ void unpk2(float& lo, float& hi, unsigned long long v) {
    unsigned l, h;
    asm("mov.b64 {%0, %1}, %2;" : "=r"(l), "=r"(h) : "l"(v));
    lo = __uint_as_float(l); hi = __uint_as_float(h);
}

// split grid barrier
__device__ __forceinline__ void gbar_arrive() {
    __syncthreads();
    if (threadIdx.x == 0) {
        asm volatile("red.release.gpu.add.u32 [%0], %1;"
                     :: "l"(&g_count), "r"(1u) : "memory");
    }
}
__device__ __forceinline__ void gbar_wait(unsigned target) {
    if (threadIdx.x == 0) {
        unsigned v;
        do {
            asm volatile("ld.acquire.gpu.u32 %0, [%1];"
                         : "=r"(v) : "l"(&g_count) : "memory");
        } while ((int)(v - target) < 0);
    }
    __syncthreads();
}

// hybrid dot body (R9)
__device__ __forceinline__ void dot32(unsigned long long acc[4][2],
                                      const float* __restrict__ wbase,
                                      const float* __restrict__ xsrc,
                                      int r4, int b4) {
#pragma unroll 8
    for (int kk = 0; kk < 32; kk++) {
        float4 wv = *(const float4*)(wbase + kk * 16 + r4);
        unsigned long long x01, x23;
        asm("ld.global.cg.v2.b64 {%0,%1}, [%2];"
            : "=l"(x01), "=l"(x23) : "l"(xsrc + kk * 32 + b4));
        unsigned long long w0p = pk2(wv.x), w1p = pk2(wv.y);
        unsigned long long w2p = pk2(wv.z), w3p = pk2(wv.w);
        fma2(acc[0][0], x01, w0p); fma2(acc[0][1], x23, w0p);
        fma2(acc[1][0], x01, w1p); fma2(acc[1][1], x23, w1p);
        fma2(acc[2][0], x01, w2p); fma2(acc[2][1], x23, w2p);
        fma2(acc[3][0], x01, w3p); fma2(acc[3][1], x23, w3p);
    }
}

__device__ __forceinline__ void store_acc(float* part, int wbase_row,
                                          unsigned long long acc[4][2],
                                          int r4, int b4) {
#pragma unroll
    for (int rr = 0; rr < 4; rr++) {
        unsigned long long* p =
            (unsigned long long*)(part + (wbase_row + r4 + rr) * PS + b4);
        p[0] = acc[rr][0];
        p[1] = acc[rr][1];
    }
}

// -------------------- setup: pack weights + init states + bf16 split --------
__global__ void k_setup(const float* __restrict__ Wih0, const float* __restrict__ Whh0,
                        const float* __restrict__ Wih1, const float* __restrict__ Whh1,
                        const float* __restrict__ bih1, const float* __restrict__ bhh1,
                        const float* __restrict__ h_t,  const float* __restrict__ c_t,
                        const float* __restrict__ hid,  const float* __restrict__ W_out,
                        const float* __restrict__ b_out) {
    int row = blockIdx.x;          // 0..2047
    int tid = threadIdx.x;         // 256 threads
    // ---- weight pack (loop weights) ----
    const float4* s1 = (const float4*)(Whh0 + (size_t)row * H_);
    float4* dW0 = (float4*)(d_W0 + (size_t)row * KC0);
    for (int i = tid; i < H_ / 4; i += 256) dW0[i] = s1[i];
    const float4* s2 = (const float4*)(Wih0 + (size_t)row * (D_ + K_) + D_);
    for (int i = tid; i < K_ / 4; i += 256) dW0[H_ / 4 + i] = s2[i];
    float4* dW1 = (float4*)(d_W1 + (size_t)row * KC1);
    const float4* s3 = (const float4*)(Wih1 + (size_t)row * H_);
    const float4* s4 = (const float4*)(Whh1 + (size_t)row * H_);
    for (int i = tid; i < H_ / 4; i += 256) { dW1[i] = s3[i]; dW1[H_ / 4 + i] = s4[i]; }
    if (tid == 0) d_bias1[row] = bih1[row] + bhh1[row];

    // ---- bf16 split of W_ih0[:, :1024] (GEMM B operand) ----
    for (int k = tid; k < 1024; k += 256) {
        float v = Wih0[(size_t)row * (D_ + K_) + k];
        __nv_bfloat16 hv = __float2bfloat16(v);
        d_Whi[(size_t)row * 1024 + k] = hv;
        d_Wlo[(size_t)row * 1024 + k] = __float2bfloat16(v - __bfloat162float(hv));
    }
    // ---- bf16 split of hiddens (GEMM A operand); 4096 elems per block ----
    {
        size_t base = (size_t)row * 4096;
        for (int i = tid; i < 4096; i += 256) {
            float v = hid[base + i];
            __nv_bfloat16 hv = __float2bfloat16(v);
            d_Ahi[base + i] = hv;
            d_Alo[base + i] = __float2bfloat16(v - __bfloat162float(hv));
        }
    }

    // ---- logits prefill with output bias (blocks 0..255 <-> t) ----
    if (row < 256) {
        float* dst = d_logits + (size_t)row * K_ * LROW;
        for (int i = tid; i < K_ * LROW; i += 256) dst[i] = b_out[i >> 7];
    }
    // ---- state transpose (blocks 0..63) ----
    if (row < 64) {
        int idx = row * 256 + tid;                 // 0..16383 = j*32+b
        int j = idx >> 5, b = idx & 31;
        d_h1[idx] = h_t[b * H_ + j];
        d_h2[idx] = h_t[B_ * H_ + b * H_ + j];
        d_c1[idx] = c_t[b * H_ + j];
        d_c2[idx] = c_t[B_ * H_ + b * H_ + j];
    }
    // ---- initial tag logits (blocks 64..95, threads 0..127) ----
    if (row >= 64 && row < 96 && tid < 128) {
        int b = row - 64;
        int k = tid;
        const float* x  = hid + (size_t)b * T_ * D_;
        const float* wr = W_out + (size_t)k * H_;
        float a0 = 0.f, a1 = 0.f, a2 = 0.f, a3 = 0.f;
        for (int j = 0; j < H_; j += 4) {
            float4 w4 = *(const float4*)(wr + j);
            a0 += w4.x * x[j + 0];
            a1 += w4.y * x[j + 1];
            a2 += w4.z * x[j + 2];
            a3 += w4.w * x[j + 3];
        }
        d_logit0[k * LROW + ((b & 3) << 5) + (b >> 2)] =
            (a0 + a1) + (a2 + a3) + b_out[k];
    }
}

// reset barrier counter
__global__ void k_zero() {
    if (threadIdx.x == 0) g_count = 0;
}

// ----------------------- mma.sync k_pre helpers ------------------------------
#define SMEM_SWZ(off) ((off) ^ (((off) >> 3) & 0x70))

__device__ __forceinline__ uint32_t smem_u32(const void* p) {
    uint32_t a;
    asm("{ .reg .u64 t; cvta.to.shared.u64 t, %1; cvt.u32.u64 %0, t; }"
        : "=r"(a) : "l"(p));
    return a;
}
__device__ __forceinline__ void lda4(uint32_t a[4], uint32_t addr) {
    asm volatile("ldmatrix.sync.aligned.m8n8.x4.shared.b16 {%0,%1,%2,%3}, [%4];"
                 : "=r"(a[0]), "=r"(a[1]), "=r"(a[2]), "=r"(a[3]) : "r"(addr));
}
__device__ __forceinline__ void ldb2(uint32_t b[2], uint32_t addr) {
    asm volatile("ldmatrix.sync.aligned.m8n8.x2.shared.b16 {%0,%1}, [%2];"
                 : "=r"(b[0]), "=r"(b[1]) : "r"(addr));
}
__device__ __forceinline__ void mma16816(float c[4], const uint32_t a[4],
                                         const uint32_t b[2]) {
    asm volatile(
        "mma.sync.aligned.m16n8k16.row.col.f32.bf16.bf16.f32 "
        "{%0,%1,%2,%3}, {%4,%5,%6,%7}, {%8,%9}, {%0,%1,%2,%3};"
        : "+f"(c[0]), "+f"(c[1]), "+f"(c[2]), "+f"(c[3])
        : "r"(a[0]), "r"(a[1]), "r"(a[2]), "r"(a[3]), "r"(b[0]), "r"(b[1]));
}

// -------- pre-projection GEMM: C[8192m x 2048n] = A x W^T, bf16-split-3 -----
#define SMP_AHI 0
#define SMP_ALO 16384
#define SMP_BHI 32768
#define SMP_BLO 40960
#define SMP_TOTAL 49152
__global__ void __launch_bounds__(256) k_preH(const float* __restrict__ bih,
                                              const float* __restrict__ bhh) {
    extern __shared__ char smem[];
    uint32_t sb = smem_u32(smem);
    int tid = threadIdx.x;
    int lane = tid & 31, w = tid >> 5;
    int n0 = blockIdx.x * 64;
    int m0 = blockIdx.y * 128;
    int wmbase = (w >> 1) * 32;    // 0,32,64,96
    int wnbase = (w & 1) * 32;     // 0,32

    int am = tid >> 1, ah = tid & 1;
    int aRowL = lane & 15;
    int aKL   = lane >> 4;
    int bRowL = lane & 7;
    int bKL   = (lane >> 3) & 1;

    float c[2][4][4];
#pragma unroll
    for (int mt = 0; mt < 2; mt++)
#pragma unroll
        for (int nt = 0; nt < 4; nt++)
#pragma unroll
            for (int i = 0; i < 4; i++) c[mt][nt][i] = 0.f;

    for (int kc = 0; kc < 16; kc++) {
        {
            const uint4* gh = (const uint4*)(d_Ahi + (size_t)(m0 + am) * 1024 + kc * 64 + ah * 32);
            const uint4* gl = (const uint4*)(d_Alo + (size_t)(m0 + am) * 1024 + kc * 64 + ah * 32);
#pragma unroll
            for (int g = 0; g < 4; g++) {
                uint32_t off = SMEM_SWZ((uint32_t)(am * 128 + (ah * 4 + g) * 16));
                *(uint4*)(smem + SMP_AHI + off) = gh[g];
                *(uint4*)(smem + SMP_ALO + off) = gl[g];
            }
#pragma unroll
            for (int i2 = 0; i2 < 2; i2++) {
                int i = tid * 2 + i2;
                int rowB = i >> 3, g = i & 7;
                const uint4* bh = (const uint4*)(d_Whi + (size_t)(n0 + rowB) * 1024 + kc * 64 + g * 8);
                const uint4* bl = (const uint4*)(d_Wlo + (size_t)(n0 + rowB) * 1024 + kc * 64 + g * 8);
                uint32_t off = SMEM_SWZ((uint32_t)(rowB * 128 + g * 16));
                *(uint4*)(smem + SMP_BHI + off) = bh[0];
                *(uint4*)(smem + SMP_BLO + off) = bl[0];
            }
        }
        __syncthreads();

#pragma unroll
        for (int ks = 0; ks < 4; ks++) {
            uint32_t aHi[2][4], aLo[2][4];
#pragma unroll
            for (int mt = 0; mt < 2; mt++) {
                int row = wmbase + mt * 16 + aRowL;
                uint32_t off = (uint32_t)(row * 128
                              + (((ks * 2 + aKL) * 16) ^ ((row & 7) << 4)));
                lda4(aHi[mt], sb + SMP_AHI + off);
                lda4(aLo[mt], sb + SMP_ALO + off);
            }
#pragma unroll
            for (int nt = 0; nt < 4; nt++) {
                uint32_t bHi[2], bLo[2];
                int row = wnbase + nt * 8 + bRowL;
                uint32_t off = (uint32_t)(row * 128
                              + (((ks * 2 + bKL) * 16) ^ ((row & 7) << 4)));
                ldb2(bHi, sb + SMP_BHI + off);
                ldb2(bLo, sb + SMP_BLO + off);
#pragma unroll
                for (int mt = 0; mt < 2; mt++) {
                    mma16816(c[mt][nt], aHi[mt], bHi);
                    mma16816(c[mt][nt], aHi[mt], bLo);
                    mma16816(c[mt][nt], aLo[mt], bHi);
                }
            }
        }
        __syncthreads();
    }

#pragma unroll
    for (int mt = 0; mt < 2; mt++) {
        int m = m0 + wmbase + mt * 16 + (lane >> 2);
        int tt = m & 255, bb = m >> 8;
        int tt8 = (m + 8) & 255;
#pragma unroll
        for (int nt = 0; nt < 4; nt++) {
            int nc = n0 + wnbase + nt * 8 + 2 * (lane & 3);
            float bz0 = bih[nc] + bhh[nc];
            float bz1 = bih[nc + 1] + bhh[nc + 1];
            d_pre0[((size_t)tt  * R_ + nc)     * B_ + bb] = c[mt][nt][0] + bz0;
            d_pre0[((size_t)tt  * R_ + nc + 1) * B_ + bb] = c[mt][nt][1] + bz1;
            d_pre0[((size_t)tt8 * R_ + nc)     * B_ + bb] = c[mt][nt][2] + bz0;
            d_pre0[((size_t)tt8 * R_ + nc + 1) * B_ + bb] = c[mt][nt][3] + bz1;
        }
    }
}

// ------------------------- persistent recurrence -----------------------------
// R9 structure; h-part row reduction (rowHA) computed in the bar2 window of the
// previous step instead of phase A.
__global__ void __launch_bounds__(512, 1) k_loop(const float* __restrict__ W_out,
                                                 const float* __restrict__ b_out) {
    extern __shared__ float smemf[];
    float* w0s     = smemf;
    float* w1s     = w0s + KC0 * 16;
    float* woutT   = w1s + KC1 * 16;
    float* bias1s  = woutT + 512;
    float* parthA  = bias1s + 32;
    float* partB   = parthA + 256 * PS;
    float* zps     = partB + 256 * PS;
    float* rowHA   = zps + 512;              // h-part rowsum (precomputed)
    float* rowH    = rowHA + 16 * PS;        // cell1 rowsum
    float* rowE    = rowH + 16 * PS;         // e-part rowsum
    float* zs      = rowE + 16 * PS;
    float* h2s     = zs + 32;

    const int c    = blockIdx.x;
    const int tid  = threadIdx.x;
    const int lane = tid & 31;
    const int w    = tid >> 5;
    const int r_   = tid >> 5;
    const int r4   = (lane >> 3) << 2;
    const int b4   = (lane & 7) << 2;
    const int bo   = ((lane & 3) << 5) + (lane >> 2);

#pragma unroll
    for (int r = 0; r < 16; r++) {
        int grow = (r >> 2) * H_ + c * 4 + (r & 3);
        const float* src0 = d_W0 + (size_t)grow * KC0;
        for (int k = tid; k < KC0; k += 512) w0s[k * 16 + r] = src0[k];
        const float* src1 = d_W1 + (size_t)grow * KC1;
        for (int k = tid; k < KC1; k += 512) w1s[k * 16 + r] = src1[k];
        if (tid == 0) bias1s[r] = d_bias1[grow];
    }
    {
        int ul2 = tid >> 7, k2 = tid & 127;
        woutT[tid] = W_out[(size_t)k2 * H_ + c * 4 + ul2];
    }
    __syncthreads();

    float c1_reg = 0.f, c2_reg = 0.f;
    int b = tid & 31, ul = tid >> 5;
    int u = c * 4 + (ul & 3);
    float pre[4];
    if (tid < 128) {
        c1_reg = d_c1[u * 32 + b];
        c2_reg = d_c2[u * 32 + b];
#pragma unroll
        for (int g = 0; g < 4; g++)
            pre[g] = __ldcg(&d_pre0[((size_t)0 * R_ + g * H_ + u) * B_ + b]);
    }

    // ---- prologue: cell0 h-part partials + rowsum for t=0 ----
    {
        unsigned long long acc[4][2];
#pragma unroll
        for (int i = 0; i < 4; i++) { acc[i][0] = 0ull; acc[i][1] = 0ull; }
        dot32(acc, w0s + (w * 32) * 16, d_h1 + (w * 32) * 32, r4, b4);
        store_acc(parthA, w * 16, acc, r4, b4);
    }
    __syncthreads();
    {
        float sh = 0.f;
#pragma unroll
        for (int w2 = 0; w2 < 16; w2++) sh += parthA[(w2 * 16 + r_) * PS + lane];
        rowHA[r_ * PS + lane] = sh;
    }
    __syncthreads();

    unsigned tgt = G_;

    for (int t = 0; t < T_; t++) {
        const int old = t & 1, nw = old ^ 1;
        float*       __restrict__ h1new = d_h1 + nw  * (H_ * B_);
        const float* __restrict__ h2old = d_h2 + old * (H_ * B_);
        float*       __restrict__ h2new = d_h2 + nw  * (H_ * B_);

        // ============== phase A: e-dot; reduce e + Z only ====================
        {
            unsigned long long acce[8];
#pragma unroll
            for (int p = 0; p < 8; p++) acce[p] = 0ull;
            const float* lg = (t == 0) ? d_logit0
                                       : d_logits + (size_t)(t - 1) * (K_ * LROW);
            float zp = 0.f;
            int ke0 = w * 8;
#pragma unroll
            for (int kk = 0; kk < 8; kk++) {
                float ev = __expf(__ldcg(lg + (ke0 + kk) * LROW + bo));
                zp += ev;
                unsigned long long xx = pk2(ev);
                const ulonglong2* q = (const ulonglong2*)(w0s + (H_ + ke0 + kk) * 16);
                ulonglong2 q0 = q[0], q1 = q[1], q2 = q[2], q3 = q[3];
                fma2(acce[0], xx, q0.x); fma2(acce[1], xx, q0.y);
                fma2(acce[2], xx, q1.x); fma2(acce[3], xx, q1.y);
                fma2(acce[4], xx, q2.x); fma2(acce[5], xx, q2.y);
                fma2(acce[6], xx, q3.x); fma2(acce[7], xx, q3.y);
            }
            zps[w * 32 + lane] = zp;
#pragma unroll
            for (int p = 0; p < 8; p++) {
                float lo, hi; unpk2(lo, hi, acce[p]);
                partB[(w * 16 + 2 * p + 0) * PS + lane] = lo;
                partB[(w * 16 + 2 * p + 1) * PS + lane] = hi;
            }
        }
        __syncthreads();

        {
            float se = 0.f;
#pragma unroll
            for (int w2 = 0; w2 < 16; w2++) se += partB[(w2 * 16 + r_) * PS + lane];
            rowE[r_ * PS + lane] = se;
            if (tid < 32) {
                float z = 0.f;
#pragma unroll
                for (int w2 = 0; w2 < 16; w2++) z += zps[w2 * 32 + tid];
                zs[tid] = z;
            }
        }
        __syncthreads();

        if (tid < 128) {
            float invZ = __fdividef(1.0f, zs[b]);
            float gate[4];
#pragma unroll
            for (int g = 0; g < 4; g++) {
                int r = g * 4 + ul;
                gate[g] = pre[g] + rowHA[r * PS + b] + rowE[r * PS + b] * invZ;
            }
            float iv = sigf(gate[0]);
            float fv = sigf(gate[1]);
            float gv = tanhfast(gate[2]);
            float ov = sigf(gate[3]);
            c1_reg = fv * c1_reg + iv * gv;
            h1new[u * 32 + b] = ov * tanhfast(c1_reg);
        }
        gbar_arrive();                          // bar1 arrive

        // ===== cell1 h2-half dot overlaps bar1 wait ==========================
        unsigned long long acc1[4][2];
#pragma unroll
        for (int i = 0; i < 4; i++) { acc1[i][0] = 0ull; acc1[i][1] = 0ull; }
        dot32(acc1, w1s + (H_ + w * 32) * 16, h2old + (w * 32) * 32, r4, b4);
        gbar_wait(tgt); tgt += G_;              // bar1 wait (h1[t] global)

        // ============== phase B: cell1 h1-half + gate1 + scatter =============
        dot32(acc1, w1s + (w * 32) * 16, h1new + (w * 32) * 32, r4, b4);
        store_acc(partB, w * 16, acc1, r4, b4);
        __syncthreads();

        {
            float s = 0.f;
#pragma unroll
            for (int w2 = 0; w2 < 16; w2++) s += partB[(w2 * 16 + r_) * PS + lane];
            rowH[r_ * PS + lane] = s;
        }
        __syncthreads();

        if (tid < 128) {
            float gate[4];
#pragma unroll
            for (int g = 0; g < 4; g++) {
                int r = g * 4 + ul;
                gate[g] = bias1s[r] + rowH[r * PS + b];
            }
            float iv = sigf(gate[0]);
            float fv = sigf(gate[1]);
            float gv = tanhfast(gate[2]);
            float ov = sigf(gate[3]);
            c2_reg = fv * c2_reg + iv * gv;
            float h2v = ov * tanhfast(c2_reg);
            h2new[u * 32 + b] = h2v;
            h2s[(ul & 3) * 32 + b] = h2v;
        }
        __syncthreads();

        {
            float h0 = h2s[lane];
            float h1v = h2s[32 + lane];
            float h2q = h2s[64 + lane];
            float h3 = h2s[96 + lane];
            float* dstl = d_logits + (size_t)t * (K_ * LROW);
            int k0 = w * 8;
#pragma unroll
            for (int kk = 0; kk < 8; kk++) {
                int kq = k0 + kk;
                float v = woutT[kq] * h0 + woutT[128 + kq] * h1v
                        + woutT[256 + kq] * h2q + woutT[384 + kq] * h3;
                atomicAdd(dstl + kq * LROW + bo, v);
            }
        }
        if (tid < 128) {
            int tn = (t + 1 < T_) ? (t + 1) : t;
#pragma unroll
            for (int g = 0; g < 4; g++)
                pre[g] = __ldcg(&d_pre0[((size_t)tn * R_ + g * H_ + u) * B_ + b]);
        }
        gbar_arrive();                          // bar2 arrive

        // ==== cell0 h-part dot + rowsum for t+1 overlap bar2 =================
        {
            unsigned long long acc[4][2];
#pragma unroll
            for (int i = 0; i < 4; i++) { acc[i][0] = 0ull; acc[i][1] = 0ull; }
            dot32(acc, w0s + (w * 32) * 16, h1new + (w * 32) * 32, r4, b4);
            store_acc(parthA, w * 16, acc, r4, b4);
        }
        __syncthreads();
        {
            float sh = 0.f;
#pragma unroll
            for (int w2 = 0; w2 < 16; w2++) sh += parthA[(w2 * 16 + r_) * PS + lane];
            rowHA[r_ * PS + lane] = sh;
        }
        gbar_wait(tgt); tgt += G_;              // bar2 wait (logits[t] global)
    }
}

// --------------------------- final masked softmax ----------------------------
__global__ void __launch_bounds__(256) k_final(const float* __restrict__ mask,
                                               float* __restrict__ out) {
    int tid = threadIdx.x, lane = tid & 31, w = tid >> 5;
    int gidx = blockIdx.x * 8 + w;
    int b = gidx >> 8, t = gidx & 255;
    float pen = (1.0f - mask[b * T_ + t]) * -1e32f;
    int bo = ((b & 3) << 5) + (b >> 2);
    float v[4];
#pragma unroll
    for (int i = 0; i < 4; i++)
        v[i] = d_logits[(size_t)t * (K_ * LROW) + (lane + 32 * i) * LROW + bo] + pen;
    float mx = fmaxf(fmaxf(v[0], v[1]), fmaxf(v[2], v[3]));
#pragma unroll
    for (int o = 16; o > 0; o >>= 1) mx = fmaxf(mx, __shfl_xor_sync(~0u, mx, o));
    float s = 0.f;
#pragma unroll
    for (int i = 0; i < 4; i++) { v[i] = __expf(v[i] - mx); s += v[i]; }
#pragma unroll
    for (int o = 16; o > 0; o >>= 1) s += __shfl_xor_sync(~0u, s, o);
    float inv = 1.0f / s;
#pragma unroll
    for (int i = 0; i < 4; i++)
        out[((size_t)b * T_ + t) * K_ + lane + 32 * i] = v[i] * inv;
}

// ----------------------------------------------------------------------------
extern "C" void kernel_launch(void* const* d_in, const int* in_sizes, int n_in,
                              void* d_out, int out_size) {
    const float* hiddens = (const float*)d_in[0];
    const float* h_t     = (const float*)d_in[1];
    const float* c_t     = (const float*)d_in[2];
    const float* mask    = (const float*)d_in[3];
    const float* W_out   = (const float*)d_in[4];
    const float* b_out   = (const float*)d_in[5];
    const float* W_ih0   = (const float*)d_in[6];
    const float* W_hh0   = (const float*)d_in[7];
    const float* b_ih0   = (const float*)d_in[8];
    const float* b_hh0   = (const float*)d_in[9];
    const float* W_ih1   = (const float*)d_in[10];
    const float* W_hh1   = (const float*)d_in[11];
    const float* b_ih1   = (const float*)d_in[12];
    const float* b_hh1   = (const float*)d_in[13];
    float* out = (float*)d_out;

    // loop SMEM floats: 10240+16384+512+32 + 8704 + 8704 + 512
    //                 + 544(rowHA) + 544(rowH) + 544(rowE) + 32 + 128 = 46880
    const int SMEM_LOOP = 46880 * 4;
    cudaFuncSetAttribute(k_loop, cudaFuncAttributeMaxDynamicSharedMemorySize, SMEM_LOOP);
    cudaFuncSetAttribute(k_preH, cudaFuncAttributeMaxDynamicSharedMemorySize, SMP_TOTAL);

    k_setup<<<R_, 256>>>(W_ih0, W_hh0, W_ih1, W_hh1, b_ih1, b_hh1,
                         h_t, c_t, hiddens, W_out, b_out);
    k_preH<<<dim3(32, 64), 256, SMP_TOTAL>>>(b_ih0, b_hh0);
    k_zero<<<1, 32>>>();
    k_loop<<<G_, 512, SMEM_LOOP>>>(W_out, b_out);
    k_final<<<1024, 256>>>(mask, out);
}

// round 16
// speedup vs baseline: 1.3013x; 1.0119x over previous
#include <cuda_runtime.h>
#include <cuda_bf16.h>
#include <cstdint>
#include <cstddef>

// ---------------------------------------------------------------------------
// TaggingFNNDecoder: 2-layer LSTM tag decoder. B=32, T=256, D=1024, H=512, K=128
// Round 15: k_preH staged via cp.async + split into 2 launches (ncu slot 4 =
// preH half 2 for evidence). Loop: e-dot logit loads batched for MLP.
// Everything else = R14.
// ---------------------------------------------------------------------------

#define B_  32
#define T_  256
#define D_  1024
#define H_  512
#define K_  128
#define R_  2048    // 4*H gate rows
#define KC0 640     // cell0 reduced k-dim: h1(512) + e(128)
#define KC1 1024    // cell1 k-dim: h1(512) + h2(512)
#define G_  128     // persistent grid size (1 CTA/SM)
#define PS  34      // padded row stride for partial arrays (8B-aligned pairs)
#define LROW 128    // interleaved logits row stride (floats per tag)

// ------------------------- device scratch ----------------------------------
__device__ float d_pre0[(size_t)T_ * R_ * B_];   // 64 MB [t][row][b]
__device__ float d_W0[(size_t)R_ * KC0];         // [row][ W_hh0 | W_ih0[:,1024:] ]
__device__ float d_W1[(size_t)R_ * KC1];         // [row][ W_ih1 | W_hh1 ]
__device__ float d_bias1[R_];
__device__ float d_h1[2 * H_ * B_];              // double buffered [j][b]
__device__ float d_h2[2 * H_ * B_];
__device__ float d_c1[H_ * B_];
__device__ float d_c2[H_ * B_];
__device__ float d_logit0[K_ * LROW];            // interleaved initial logits
__device__ float d_logits[(size_t)T_ * K_ * LROW]; // interleaved raw logits

// bf16 split operands for the HMMA pre-projection GEMM
__device__ __nv_bfloat16 d_Ahi[(size_t)8192 * 1024];   // 16 MB
__device__ __nv_bfloat16 d_Alo[(size_t)8192 * 1024];   // 16 MB
__device__ __nv_bfloat16 d_Whi[(size_t)R_ * 1024];     // 4 MB
__device__ __nv_bfloat16 d_Wlo[(size_t)R_ * 1024];     // 4 MB

// central barrier counter (monotonic within one launch; reset by k_zero)
__device__ unsigned g_count;

// fast NaN-free activations
__device__ __forceinline__ float sigf(float x) {
    return __fdividef(1.0f, 1.0f + __expf(-x));
}
__device__ __forceinline__ float tanhfast(float x) {
    return 1.0f - __fdividef(2.0f, 1.0f + __expf(2.0f * x));
}

// packed fp32x2 helpers
__device__ __forceinline__ unsigned long long pk2(float x) {
    unsigned long long r; unsigned u = __float_as_uint(x);
    asm("mov.b64 %0, {%1, %1};" : "=l"(r) : "r"(u));
    return r;
}
__device__ __forceinline__ void fma2(unsigned long long& a,
                                     unsigned long long x, unsigned long long w) {
    asm("fma.rn.f32x2 %0, %1, %2, %0;" : "+l"(a) : "l"(x), "l"(w));
}
__device__ __forceinline__ void unpk2(float& lo, float& hi, unsigned long long v) {
    unsigned l, h;
    asm("mov.b64 {%0, %1}, %2;" : "=r"(l), "=r"(h) : "l"(v));
    lo = __uint_as_float(l); hi = __uint_as_float(h);
}

// split grid barrier
__device__ __forceinline__ void gbar_arrive() {
    __syncthreads();
    if (threadIdx.x == 0) {
        asm volatile("red.release.gpu.add.u32 [%0], %1;"
                     :: "l"(&g_count), "r"(1u) : "memory");
    }
}
__device__ __forceinline__ void gbar_wait(unsigned target) {
    if (threadIdx.x == 0) {
        unsigned v;
        do {
            asm volatile("ld.acquire.gpu.u32 %0, [%1];"
                         : "=r"(v) : "l"(&g_count) : "memory");
        } while ((int)(v - target) < 0);
    }
    __syncthreads();
}

// hybrid dot body (R9)
__device__ __forceinline__ void dot32(unsigned long long acc[4][2],
                                      const float* __restrict__ wbase,
                                      const float* __restrict__ xsrc,
                                      int r4, int b4) {
#pragma unroll 8
    for (int kk = 0; kk < 32; kk++) {
        float4 wv = *(const float4*)(wbase + kk * 16 + r4);
        unsigned long long x01, x23;
        asm("ld.global.cg.v2.b64 {%0,%1}, [%2];"
            : "=l"(x01), "=l"(x23) : "l"(xsrc + kk * 32 + b4));
        unsigned long long w0p = pk2(wv.x), w1p = pk2(wv.y);
        unsigned long long w2p = pk2(wv.z), w3p = pk2(wv.w);
        fma2(acc[0][0], x01, w0p); fma2(acc[0][1], x23, w0p);
        fma2(acc[1][0], x01, w1p); fma2(acc[1][1], x23, w1p);
        fma2(acc[2][0], x01, w2p); fma2(acc[2][1], x23, w2p);
        fma2(acc[3][0], x01, w3p); fma2(acc[3][1], x23, w3p);
    }
}

__device__ __forceinline__ void store_acc(float* part, int wbase_row,
                                          unsigned long long acc[4][2],
                                          int r4, int b4) {
#pragma unroll
    for (int rr = 0; rr < 4; rr++) {
        unsigned long long* p =
            (unsigned long long*)(part + (wbase_row + r4 + rr) * PS + b4);
        p[0] = acc[rr][0];
        p[1] = acc[rr][1];
    }
}

// -------------------- setup: pack weights + init states + bf16 split --------
__global__ void k_setup(const float* __restrict__ Wih0, const float* __restrict__ Whh0,
                        const float* __restrict__ Wih1, const float* __restrict__ Whh1,
                        const float* __restrict__ bih1, const float* __restrict__ bhh1,
                        const float* __restrict__ h_t,  const float* __restrict__ c_t,
                        const float* __restrict__ hid,  const float* __restrict__ W_out,
                        const float* __restrict__ b_out) {
    int row = blockIdx.x;          // 0..2047
    int tid = threadIdx.x;         // 256 threads
    // ---- weight pack (loop weights) ----
    const float4* s1 = (const float4*)(Whh0 + (size_t)row * H_);
    float4* dW0 = (float4*)(d_W0 + (size_t)row * KC0);
    for (int i = tid; i < H_ / 4; i += 256) dW0[i] = s1[i];
    const float4* s2 = (const float4*)(Wih0 + (size_t)row * (D_ + K_) + D_);
    for (int i = tid; i < K_ / 4; i += 256) dW0[H_ / 4 + i] = s2[i];
    float4* dW1 = (float4*)(d_W1 + (size_t)row * KC1);
    const float4* s3 = (const float4*)(Wih1 + (size_t)row * H_);
    const float4* s4 = (const float4*)(Whh1 + (size_t)row * H_);
    for (int i = tid; i < H_ / 4; i += 256) { dW1[i] = s3[i]; dW1[H_ / 4 + i] = s4[i]; }
    if (tid == 0) d_bias1[row] = bih1[row] + bhh1[row];

    // ---- bf16 split of W_ih0[:, :1024] (GEMM B operand) ----
    for (int k = tid; k < 1024; k += 256) {
        float v = Wih0[(size_t)row * (D_ + K_) + k];
        __nv_bfloat16 hv = __float2bfloat16(v);
        d_Whi[(size_t)row * 1024 + k] = hv;
        d_Wlo[(size_t)row * 1024 + k] = __float2bfloat16(v - __bfloat162float(hv));
    }
    // ---- bf16 split of hiddens (GEMM A operand); 4096 elems per block ----
    {
        size_t base = (size_t)row * 4096;
        for (int i = tid; i < 4096; i += 256) {
            float v = hid[base + i];
            __nv_bfloat16 hv = __float2bfloat16(v);
            d_Ahi[base + i] = hv;
            d_Alo[base + i] = __float2bfloat16(v - __bfloat162float(hv));
        }
    }

    // ---- logits prefill with output bias (blocks 0..255 <-> t), float4 ----
    if (row < 256) {
        float4* dst = (float4*)(d_logits + (size_t)row * K_ * LROW);
        for (int i = tid; i < K_ * LROW / 4; i += 256) {
            float bv = b_out[i >> 5];
            dst[i] = make_float4(bv, bv, bv, bv);
        }
    }
    // ---- state transpose (blocks 0..63) ----
    if (row < 64) {
        int idx = row * 256 + tid;                 // 0..16383 = j*32+b
        int j = idx >> 5, b = idx & 31;
        d_h1[idx] = h_t[b * H_ + j];
        d_h2[idx] = h_t[B_ * H_ + b * H_ + j];
        d_c1[idx] = c_t[b * H_ + j];
        d_c2[idx] = c_t[B_ * H_ + b * H_ + j];
    }
    // ---- initial tag logits (blocks 64..95, threads 0..127) ----
    if (row >= 64 && row < 96 && tid < 128) {
        int b = row - 64;
        int k = tid;
        const float* x  = hid + (size_t)b * T_ * D_;
        const float* wr = W_out + (size_t)k * H_;
        float a0 = 0.f, a1 = 0.f, a2 = 0.f, a3 = 0.f;
        for (int j = 0; j < H_; j += 4) {
            float4 w4 = *(const float4*)(wr + j);
            a0 += w4.x * x[j + 0];
            a1 += w4.y * x[j + 1];
            a2 += w4.z * x[j + 2];
            a3 += w4.w * x[j + 3];
        }
        d_logit0[k * LROW + ((b & 3) << 5) + (b >> 2)] =
            (a0 + a1) + (a2 + a3) + b_out[k];
    }
}

// reset barrier counter
__global__ void k_zero() {
    if (threadIdx.x == 0) g_count = 0;
}

// ----------------------- mma.sync k_pre helpers ------------------------------
#define SMEM_SWZ(off) ((off) ^ (((off) >> 3) & 0x70))

__device__ __forceinline__ uint32_t smem_u32(const void* p) {
    uint32_t a;
    asm("{ .reg .u64 t; cvta.to.shared.u64 t, %1; cvt.u32.u64 %0, t; }"
        : "=r"(a) : "l"(p));
    return a;
}
__device__ __forceinline__ void cpasync16(uint32_t dst, const void* src) {
    asm volatile("cp.async.ca.shared.global [%0], [%1], 16;"
                 :: "r"(dst), "l"(src) : "memory");
}
__device__ __forceinline__ void lda4(uint32_t a[4], uint32_t addr) {
    asm volatile("ldmatrix.sync.aligned.m8n8.x4.shared.b16 {%0,%1,%2,%3}, [%4];"
                 : "=r"(a[0]), "=r"(a[1]), "=r"(a[2]), "=r"(a[3]) : "r"(addr));
}
__device__ __forceinline__ void ldb2(uint32_t b[2], uint32_t addr) {
    asm volatile("ldmatrix.sync.aligned.m8n8.x2.shared.b16 {%0,%1}, [%2];"
                 : "=r"(b[0]), "=r"(b[1]) : "r"(addr));
}
__device__ __forceinline__ void mma16816(float c[4], const uint32_t a[4],
                                         const uint32_t b[2]) {
    asm volatile(
        "mma.sync.aligned.m16n8k16.row.col.f32.bf16.bf16.f32 "
        "{%0,%1,%2,%3}, {%4,%5,%6,%7}, {%8,%9}, {%0,%1,%2,%3};"
        : "+f"(c[0]), "+f"(c[1]), "+f"(c[2]), "+f"(c[3])
        : "r"(a[0]), "r"(a[1]), "r"(a[2]), "r"(a[3]), "r"(b[0]), "r"(b[1]));
}

// -------- pre-projection GEMM: C[8192m x 2048n] = A x W^T, bf16-split-3 -----
// cp.async staging; launched twice with n_base = 0, 16 (16 n-blocks each).
#define SMP_AHI 0
#define SMP_ALO 16384
#define SMP_BHI 32768
#define SMP_BLO 40960
#define SMP_TOTAL 49152
__global__ void __launch_bounds__(256) k_preH(const float* __restrict__ bih,
                                              const float* __restrict__ bhh,
                                              int n_base) {
    extern __shared__ char smem[];
    uint32_t sb = smem_u32(smem);
    int tid = threadIdx.x;
    int lane = tid & 31, w = tid >> 5;
    int n0 = (n_base + blockIdx.x) * 64;
    int m0 = blockIdx.y * 128;
    int wmbase = (w >> 1) * 32;    // 0,32,64,96
    int wnbase = (w & 1) * 32;     // 0,32

    int am = tid >> 1, ah = tid & 1;
    int aRowL = lane & 15;
    int aKL   = lane >> 4;
    int bRowL = lane & 7;
    int bKL   = (lane >> 3) & 1;

    // precompute staging addresses (invariant across kc except +64 elements)
    int rowB2 = tid >> 2, gB = (tid & 3) * 2;     // B: thread covers 2 g-slots

    float c[2][4][4];
#pragma unroll
    for (int mt = 0; mt < 2; mt++)
#pragma unroll
        for (int nt = 0; nt < 4; nt++)
#pragma unroll
            for (int i = 0; i < 4; i++) c[mt][nt][i] = 0.f;

    for (int kc = 0; kc < 16; kc++) {
        // ---- stage chunk via cp.async ----
        {
            const __nv_bfloat16* gha = d_Ahi + (size_t)(m0 + am) * 1024 + kc * 64 + ah * 32;
            const __nv_bfloat16* gla = d_Alo + (size_t)(m0 + am) * 1024 + kc * 64 + ah * 32;
#pragma unroll
            for (int g = 0; g < 4; g++) {
                uint32_t off = SMEM_SWZ((uint32_t)(am * 128 + (ah * 4 + g) * 16));
                cpasync16(sb + SMP_AHI + off, gha + g * 8);
                cpasync16(sb + SMP_ALO + off, gla + g * 8);
            }
            const __nv_bfloat16* ghb = d_Whi + (size_t)(n0 + rowB2) * 1024 + kc * 64 + gB * 8;
            const __nv_bfloat16* glb = d_Wlo + (size_t)(n0 + rowB2) * 1024 + kc * 64 + gB * 8;
#pragma unroll
            for (int g = 0; g < 2; g++) {
                uint32_t off = SMEM_SWZ((uint32_t)(rowB2 * 128 + (gB + g) * 16));
                cpasync16(sb + SMP_BHI + off, ghb + g * 8);
                cpasync16(sb + SMP_BLO + off, glb + g * 8);
            }
            asm volatile("cp.async.commit_group;" ::: "memory");
            asm volatile("cp.async.wait_group 0;" ::: "memory");
        }
        __syncthreads();

#pragma unroll
        for (int ks = 0; ks < 4; ks++) {
            uint32_t aHi[2][4], aLo[2][4];
#pragma unroll
            for (int mt = 0; mt < 2; mt++) {
                int row = wmbase + mt * 16 + aRowL;
                uint32_t off = (uint32_t)(row * 128
                              + (((ks * 2 + aKL) * 16) ^ ((row & 7) << 4)));
                lda4(aHi[mt], sb + SMP_AHI + off);
                lda4(aLo[mt], sb + SMP_ALO + off);
            }
#pragma unroll
            for (int nt = 0; nt < 4; nt++) {
                uint32_t bHi[2], bLo[2];
                int row = wnbase + nt * 8 + bRowL;
                uint32_t off = (uint32_t)(row * 128
                              + (((ks * 2 + bKL) * 16) ^ ((row & 7) << 4)));
                ldb2(bHi, sb + SMP_BHI + off);
                ldb2(bLo, sb + SMP_BLO + off);
#pragma unroll
                for (int mt = 0; mt < 2; mt++) {
                    mma16816(c[mt][nt], aHi[mt], bHi);
                    mma16816(c[mt][nt], aHi[mt], bLo);
                    mma16816(c[mt][nt], aLo[mt], bHi);
                }
            }
        }
        __syncthreads();
    }

#pragma unroll
    for (int mt = 0; mt < 2; mt++) {
        int m = m0 + wmbase + mt * 16 + (lane >> 2);
        int tt = m & 255, bb = m >> 8;
        int tt8 = (m + 8) & 255;
#pragma unroll
        for (int nt = 0; nt < 4; nt++) {
            int nc = n0 + wnbase + nt * 8 + 2 * (lane & 3);
            float bz0 = bih[nc] + bhh[nc];
            float bz1 = bih[nc + 1] + bhh[nc + 1];
            d_pre0[((size_t)tt  * R_ + nc)     * B_ + bb] = c[mt][nt][0] + bz0;
            d_pre0[((size_t)tt  * R_ + nc + 1) * B_ + bb] = c[mt][nt][1] + bz1;
            d_pre0[((size_t)tt8 * R_ + nc)     * B_ + bb] = c[mt][nt][2] + bz0;
            d_pre0[((size_t)tt8 * R_ + nc + 1) * B_ + bb] = c[mt][nt][3] + bz1;
        }
    }
}

// ------------------------- persistent recurrence -----------------------------
__global__ void __launch_bounds__(512, 1) k_loop(const float* __restrict__ W_out,
                                                 const float* __restrict__ b_out) {
    extern __shared__ float smemf[];
    float* w0s     = smemf;
    float* w1s     = w0s + KC0 * 16;
    float* woutT   = w1s + KC1 * 16;
    float* bias1s  = woutT + 512;
    float* parthA  = bias1s + 32;
    float* partB   = parthA + 256 * PS;
    float* zps     = partB + 256 * PS;
    float* rowHA   = zps + 512;
    float* rowH    = rowHA + 16 * PS;
    float* rowE    = rowH + 16 * PS;
    float* zs      = rowE + 16 * PS;
    float* h2s     = zs + 32;

    const int c    = blockIdx.x;
    const int tid  = threadIdx.x;
    const int lane = tid & 31;
    const int w    = tid >> 5;
    const int r_   = tid >> 5;
    const int r4   = (lane >> 3) << 2;
    const int b4   = (lane & 7) << 2;
    const int bo   = ((lane & 3) << 5) + (lane >> 2);

#pragma unroll
    for (int r = 0; r < 16; r++) {
        int grow = (r >> 2) * H_ + c * 4 + (r & 3);
        const float* src0 = d_W0 + (size_t)grow * KC0;
        for (int k = tid; k < KC0; k += 512) w0s[k * 16 + r] = src0[k];
        const float* src1 = d_W1 + (size_t)grow * KC1;
        for (int k = tid; k < KC1; k += 512) w1s[k * 16 + r] = src1[k];
        if (tid == 0) bias1s[r] = d_bias1[grow];
    }
    {
        int ul2 = tid >> 7, k2 = tid & 127;
        woutT[tid] = W_out[(size_t)k2 * H_ + c * 4 + ul2];
    }
    __syncthreads();

    float c1_reg = 0.f, c2_reg = 0.f;
    int b = tid & 31, ul = tid >> 5;
    int u = c * 4 + (ul & 3);
    float pre[4];
    if (tid < 128) {
        c1_reg = d_c1[u * 32 + b];
        c2_reg = d_c2[u * 32 + b];
#pragma unroll
        for (int g = 0; g < 4; g++)
            pre[g] = __ldcg(&d_pre0[((size_t)0 * R_ + g * H_ + u) * B_ + b]);
    }

    // ---- prologue: cell0 h-part partials + rowsum for t=0 ----
    {
        unsigned long long acc[4][2];
#pragma unroll
        for (int i = 0; i < 4; i++) { acc[i][0] = 0ull; acc[i][1] = 0ull; }
        dot32(acc, w0s + (w * 32) * 16, d_h1 + (w * 32) * 32, r4, b4);
        store_acc(parthA, w * 16, acc, r4, b4);
    }
    __syncthreads();
    {
        float sh = 0.f;
#pragma unroll
        for (int w2 = 0; w2 < 16; w2++) sh += parthA[(w2 * 16 + r_) * PS + lane];
        rowHA[r_ * PS + lane] = sh;
    }
    __syncthreads();

    unsigned tgt = G_;

    for (int t = 0; t < T_; t++) {
        const int old = t & 1, nw = old ^ 1;
        float*       __restrict__ h1new = d_h1 + nw  * (H_ * B_);
        const float* __restrict__ h2old = d_h2 + old * (H_ * B_);
        float*       __restrict__ h2new = d_h2 + nw  * (H_ * B_);

        // ============== phase A: e-dot (batched loads); reduce e + Z =========
        {
            unsigned long long acce[8];
#pragma unroll
            for (int p = 0; p < 8; p++) acce[p] = 0ull;
            const float* lg = (t == 0) ? d_logit0
                                       : d_logits + (size_t)(t - 1) * (K_ * LROW);
            int ke0 = w * 8;
            float lv[8];
#pragma unroll
            for (int kk = 0; kk < 8; kk++)
                lv[kk] = __ldcg(lg + (ke0 + kk) * LROW + bo);
            float zp = 0.f;
#pragma unroll
            for (int kk = 0; kk < 8; kk++) {
                float ev = __expf(lv[kk]);
                zp += ev;
                unsigned long long xx = pk2(ev);
                const ulonglong2* q = (const ulonglong2*)(w0s + (H_ + ke0 + kk) * 16);
                ulonglong2 q0 = q[0], q1 = q[1], q2 = q[2], q3 = q[3];
                fma2(acce[0], xx, q0.x); fma2(acce[1], xx, q0.y);
                fma2(acce[2], xx, q1.x); fma2(acce[3], xx, q1.y);
                fma2(acce[4], xx, q2.x); fma2(acce[5], xx, q2.y);
                fma2(acce[6], xx, q3.x); fma2(acce[7], xx, q3.y);
            }
            zps[w * 32 + lane] = zp;
#pragma unroll
            for (int p = 0; p < 8; p++) {
                float lo, hi; unpk2(lo, hi, acce[p]);
                partB[(w * 16 + 2 * p + 0) * PS + lane] = lo;
                partB[(w * 16 + 2 * p + 1) * PS + lane] = hi;
            }
        }
        __syncthreads();

        {
            float se = 0.f;
#pragma unroll
            for (int w2 = 0; w2 < 16; w2++) se += partB[(w2 * 16 + r_) * PS + lane];
            rowE[r_ * PS + lane] = se;
            if (tid < 32) {
                float z = 0.f;
#pragma unroll
                for (int w2 = 0; w2 < 16; w2++) z += zps[w2 * 32 + tid];
                zs[tid] = z;
            }
        }
        __syncthreads();

        if (tid < 128) {
            float invZ = __fdividef(1.0f, zs[b]);
            float gate[4];
#pragma unroll
            for (int g = 0; g < 4; g++) {
                int r = g * 4 + ul;
                gate[g] = pre[g] + rowHA[r * PS + b] + rowE[r * PS + b] * invZ;
            }
            float iv = sigf(gate[0]);
            float fv = sigf(gate[1]);
            float gv = tanhfast(gate[2]);
            float ov = sigf(gate[3]);
            c1_reg = fv * c1_reg + iv * gv;
            h1new[u * 32 + b] = ov * tanhfast(c1_reg);
        }
        gbar_arrive();                          // bar1 arrive

        // ===== cell1 h2-half dot overlaps bar1 wait ==========================
        unsigned long long acc1[4][2];
#pragma unroll
        for (int i = 0; i < 4; i++) { acc1[i][0] = 0ull; acc1[i][1] = 0ull; }
        dot32(acc1, w1s + (H_ + w * 32) * 16, h2old + (w * 32) * 32, r4, b4);
        gbar_wait(tgt); tgt += G_;              // bar1 wait (h1[t] global)

        // ============== phase B: cell1 h1-half + gate1 + scatter =============
        dot32(acc1, w1s + (w * 32) * 16, h1new + (w * 32) * 32, r4, b4);
        store_acc(partB, w * 16, acc1, r4, b4);
        __syncthreads();

        {
            float s = 0.f;
#pragma unroll
            for (int w2 = 0; w2 < 16; w2++) s += partB[(w2 * 16 + r_) * PS + lane];
            rowH[r_ * PS + lane] = s;
        }
        __syncthreads();

        if (tid < 128) {
            float gate[4];
#pragma unroll
            for (int g = 0; g < 4; g++) {
                int r = g * 4 + ul;
                gate[g] = bias1s[r] + rowH[r * PS + b];
            }
            float iv = sigf(gate[0]);
            float fv = sigf(gate[1]);
            float gv = tanhfast(gate[2]);
            float ov = sigf(gate[3]);
            c2_reg = fv * c2_reg + iv * gv;
            float h2v = ov * tanhfast(c2_reg);
            h2new[u * 32 + b] = h2v;
            h2s[(ul & 3) * 32 + b] = h2v;
        }
        __syncthreads();

        {
            float h0 = h2s[lane];
            float h1v = h2s[32 + lane];
            float h2q = h2s[64 + lane];
            float h3 = h2s[96 + lane];
            float* dstl = d_logits + (size_t)t * (K_ * LROW);
            int k0 = w * 8;
#pragma unroll
            for (int kk = 0; kk < 8; kk++) {
                int kq = k0 + kk;
                float v = woutT[kq] * h0 + woutT[128 + kq] * h1v
                        + woutT[256 + kq] * h2q + woutT[384 + kq] * h3;
                atomicAdd(dstl + kq * LROW + bo, v);
            }
        }
        if (tid < 128) {
            int tn = (t + 1 < T_) ? (t + 1) : t;
#pragma unroll
            for (int g = 0; g < 4; g++)
                pre[g] = __ldcg(&d_pre0[((size_t)tn * R_ + g * H_ + u) * B_ + b]);
        }
        gbar_arrive();                          // bar2 arrive

        // ==== cell0 h-part dot + rowsum for t+1 overlap bar2 =================
        {
            unsigned long long acc[4][2];
#pragma unroll
            for (int i = 0; i < 4; i++) { acc[i][0] = 0ull; acc[i][1] = 0ull; }
            dot32(acc, w0s + (w * 32) * 16, h1new + (w * 32) * 32, r4, b4);
            store_acc(parthA, w * 16, acc, r4, b4);
        }
        __syncthreads();
        {
            float sh = 0.f;
#pragma unroll
            for (int w2 = 0; w2 < 16; w2++) sh += parthA[(w2 * 16 + r_) * PS + lane];
            rowHA[r_ * PS + lane] = sh;
        }
        gbar_wait(tgt); tgt += G_;              // bar2 wait (logits[t] global)
    }
}

// --------------------------- final masked softmax ----------------------------
__global__ void __launch_bounds__(256) k_final(const float* __restrict__ mask,
                                               float* __restrict__ out) {
    int tid = threadIdx.x, lane = tid & 31, w = tid >> 5;
    int gidx = blockIdx.x * 8 + w;
    int b = gidx >> 8, t = gidx & 255;
    float pen = (1.0f - mask[b * T_ + t]) * -1e32f;
    int bo = ((b & 3) << 5) + (b >> 2);
    float v[4];
#pragma unroll
    for (int i = 0; i < 4; i++)
        v[i] = d_logits[(size_t)t * (K_ * LROW) + (lane + 32 * i) * LROW + bo] + pen;
    float mx = fmaxf(fmaxf(v[0], v[1]), fmaxf(v[2], v[3]));
#pragma unroll
    for (int o = 16; o > 0; o >>= 1) mx = fmaxf(mx, __shfl_xor_sync(~0u, mx, o));
    float s = 0.f;
#pragma unroll
    for (int i = 0; i < 4; i++) { v[i] = __expf(v[i] - mx); s += v[i]; }
#pragma unroll
    for (int o = 16; o > 0; o >>= 1) s += __shfl_xor_sync(~0u, s, o);
    float inv = 1.0f / s;
#pragma unroll
    for (int i = 0; i < 4; i++)
        out[((size_t)b * T_ + t) * K_ + lane + 32 * i] = v[i] * inv;
}

// ----------------------------------------------------------------------------
extern "C" void kernel_launch(void* const* d_in, const int* in_sizes, int n_in,
                              void* d_out, int out_size) {
    const float* hiddens = (const float*)d_in[0];
    const float* h_t     = (const float*)d_in[1];
    const float* c_t     = (const float*)d_in[2];
    const float* mask    = (const float*)d_in[3];
    const float* W_out   = (const float*)d_in[4];
    const float* b_out   = (const float*)d_in[5];
    const float* W_ih0   = (const float*)d_in[6];
    const float* W_hh0   = (const float*)d_in[7];
    const float* b_ih0   = (const float*)d_in[8];
    const float* b_hh0   = (const float*)d_in[9];
    const float* W_ih1   = (const float*)d_in[10];
    const float* W_hh1   = (const float*)d_in[11];
    const float* b_ih1   = (const float*)d_in[12];
    const float* b_hh1   = (const float*)d_in[13];
    float* out = (float*)d_out;

    const int SMEM_LOOP = 46880 * 4;   // same as R14
    cudaFuncSetAttribute(k_loop, cudaFuncAttributeMaxDynamicSharedMemorySize, SMEM_LOOP);
    cudaFuncSetAttribute(k_preH, cudaFuncAttributeMaxDynamicSharedMemorySize, SMP_TOTAL);

    // order: slot 4 (ncu capture) = k_preH(half 2)
    k_setup<<<R_, 256>>>(W_ih0, W_hh0, W_ih1, W_hh1, b_ih1, b_hh1,
                         h_t, c_t, hiddens, W_out, b_out);
    k_zero<<<1, 32>>>();
    k_preH<<<dim3(16, 64), 256, SMP_TOTAL>>>(b_ih0, b_hh0, 0);
    k_preH<<<dim3(16, 64), 256, SMP_TOTAL>>>(b_ih0, b_hh0, 16);
    k_loop<<<G_, 512, SMEM_LOOP>>>(W_out, b_out);
    k_final<<<1024, 256>>>(mask, out);
}